// round 14
// baseline (speedup 1.0000x reference)
#include <cuda_runtime.h>
#include <cuda_fp16.h>
#include <cstdint>
#include <cstddef>

// ---------------- problem constants ----------------
#define D_MODEL 768
#define D_INNER 1536
#define D_STATE 16
#define DT_RANK 48
#define NB 2
#define SEQ 1024
#define BL (NB * SEQ)                 // 2048
#define KIN  D_MODEL                  // 768
#define KIN2 (2 * KIN)                // 1536
#define KOUT D_INNER                  // 1536
#define KOUT2 (2 * KOUT)              // 3072
#define DBC_PAD 256
#define XPROJ_SPLITK 8

// ---------------- scratch (static __device__ arrays; zero-initialized) ----------------
__device__ __half g_inp[BL * 2 * D_INNER];          // in_proj output (fp16)
__device__ __half g_zs[BL * D_INNER];
__device__ __half g_dbcp[XPROJ_SPLITK * BL * DBC_PAD];  // x_proj partials (fp16)
__device__ float g_dbc_bc[BL * 64];
__device__ __half g_delta_f[BL * D_INNER];
__device__ __half g_delta_b[BL * D_INNER];
__device__ __half g_y_f[BL * D_INNER];
__device__ __half g_y_b[BL * D_INNER];
__device__ __half g_opart[3 * BL * D_MODEL];        // out_proj slices (fp16)
__device__ __half g_ax[BL * KIN2];
__device__ __half g_wi[2 * D_INNER * KIN2];
__device__ __half g_xsc16[BL * KOUT2];
__device__ __half g_w3[DBC_PAD * KOUT2];
__device__ __half g_wdt_f[D_INNER * 2 * DT_RANK];
__device__ __half g_wdt_b[D_INNER * 2 * DT_RANK];
__device__ __half g_dbc48_f[BL * 2 * DT_RANK];
__device__ __half g_dbc48_b[BL * 2 * DT_RANK];
__device__ __half g_u2[BL * KOUT2];
__device__ __half g_wo[D_MODEL * KOUT2];

// ---------------- math helpers ----------------
__device__ __forceinline__ float siluf(float x) { return x / (1.f + __expf(-x)); }
__device__ __forceinline__ float softplusf(float x) {
    return (x > 20.f) ? x : log1pf(__expf(x));
}
__device__ __forceinline__ uint32_t smem_u32(const void* p) {
    uint32_t a;
    asm("{ .reg .u64 t; cvta.to.shared.u64 t, %1; cvt.u32.u64 %0, t; }" : "=r"(a) : "l"(p));
    return a;
}
__device__ __forceinline__ void cp_async16(uint32_t saddr, const void* g) {
    asm volatile("cp.async.cg.shared.global [%0], [%1], 16;" :: "r"(saddr), "l"(g));
}
__device__ __forceinline__ void cp_commit() {
    asm volatile("cp.async.commit_group;" ::: "memory");
}
__device__ __forceinline__ void ldm_x4(uint32_t& r0, uint32_t& r1, uint32_t& r2,
                                       uint32_t& r3, uint32_t addr) {
    asm volatile("ldmatrix.sync.aligned.m8n8.x4.shared.b16 {%0,%1,%2,%3}, [%4];"
                 : "=r"(r0), "=r"(r1), "=r"(r2), "=r"(r3) : "r"(addr));
}
__device__ __forceinline__ void mma_f16(float* c, const uint32_t* a, const uint32_t* b) {
    asm volatile(
        "mma.sync.aligned.m16n8k16.row.col.f32.f16.f16.f32 "
        "{%0,%1,%2,%3}, {%4,%5,%6,%7}, {%8,%9}, {%0,%1,%2,%3};"
        : "+f"(c[0]), "+f"(c[1]), "+f"(c[2]), "+f"(c[3])
        : "r"(a[0]), "r"(a[1]), "r"(a[2]), "r"(a[3]), "r"(b[0]), "r"(b[1]));
}
__device__ __forceinline__ void split_h(float v, unsigned short& hi, unsigned short& lo) {
    __half h = __float2half_rn(v);
    __half l = __float2half_rn(v - __half2float(h));
    hi = __half_as_ushort(h); lo = __half_as_ushort(l);
}

// ---------------- HMMA fp16 GEMM ----------------
// EPI: 0 = fp32 store, 2 = softplus(v+bias)->half, 3 = plain half store.
// ZMODE: 0 = split-K slices; 1 = two problems.
// SKIP80: skip stores where (gcol & 127) >= 80.
#define ROWB 80
#define STAGE_BYTES 20480
#define OFFB 10240
template <int EPI, int ZMODE, int SKIP80>
__global__ void __launch_bounds__(256) hmma_f16_nt(
    const __half* __restrict__ A,
    const __half* __restrict__ B,
    float* __restrict__ C, int ldc, int Kp, int nChunks, long long zstride,
    const float* __restrict__ bias,
    const __half* __restrict__ A2, const __half* __restrict__ B2,
    float* __restrict__ C2, const float* __restrict__ bias2)
{
    extern __shared__ char smem[];
    const uint32_t sb = smem_u32(smem);
    const int tid = threadIdx.x;
    const int rowBase = blockIdx.y * 128;
    const int colBase = blockIdx.x * 128;
    float* Cw = nullptr;
    __half* CwH = nullptr;
    int chunkBase;
    if (ZMODE == 1) {
        if (blockIdx.z == 1) { A = A2; B = B2; C = C2; bias = bias2; }
        if (EPI == 3 || EPI == 2) CwH = (__half*)C; else Cw = C;
        chunkBase = 0;
    } else {
        if (EPI == 3) CwH = (__half*)C + (size_t)blockIdx.z * (size_t)zstride;
        else Cw = C + (size_t)blockIdx.z * (size_t)zstride;
        chunkBase = blockIdx.z * nChunks;
    }

    const int r0 = tid >> 2, c0 = tid & 3;
    const int r1 = (tid + 256) >> 2, c1 = (tid + 256) & 3;
    const char* gA0 = (const char*)(A + (size_t)(rowBase + r0) * Kp + c0 * 8)
                      + (size_t)chunkBase * 64;
    const char* gA1 = (const char*)(A + (size_t)(rowBase + r1) * Kp + c1 * 8)
                      + (size_t)chunkBase * 64;
    const char* gB0 = (const char*)(B + (size_t)(colBase + r0) * Kp + c0 * 8)
                      + (size_t)chunkBase * 64;
    const char* gB1 = (const char*)(B + (size_t)(colBase + r1) * Kp + c1 * 8)
                      + (size_t)chunkBase * 64;
    const uint32_t sA0 = r0 * ROWB + c0 * 16, sA1 = r1 * ROWB + c1 * 16;
    const uint32_t sB0 = OFFB + sA0, sB1 = OFFB + sA1;

#define LOAD_STAGE(c) do {                                                  \
    const uint32_t _base = sb + ((c) & 3) * STAGE_BYTES;                    \
    const size_t _gk = (size_t)(c) * 64;                                    \
    cp_async16(_base + sA0, gA0 + _gk);                                     \
    cp_async16(_base + sA1, gA1 + _gk);                                     \
    cp_async16(_base + sB0, gB0 + _gk);                                     \
    cp_async16(_base + sB1, gB1 + _gk);                                     \
} while (0)

    const int wid = tid >> 5;
    const int l = tid & 31;
    const int wm = wid & 3;
    const int wn = wid >> 2;
    const int a_row = ((l >> 3) & 1) * 8 + (l & 7);
    const int a_k   = (l >> 4) * 8;
    const int b_n   = (l >> 4) * 8 + (l & 7);
    const int b_k   = ((l >> 3) & 1) * 8;

    float acc[2][8][4];
#pragma unroll
    for (int i = 0; i < 2; i++)
#pragma unroll
        for (int j = 0; j < 8; j++)
#pragma unroll
            for (int q = 0; q < 4; q++) acc[i][j][q] = 0.f;

    LOAD_STAGE(0); cp_commit();
    if (nChunks > 1) LOAD_STAGE(1);
    cp_commit();
    if (nChunks > 2) LOAD_STAGE(2);
    cp_commit();

    for (int c = 0; c < nChunks; c++) {
        asm volatile("cp.async.wait_group 2;" ::: "memory");
        __syncthreads();
        if (c + 3 < nChunks) LOAD_STAGE(c + 3);
        cp_commit();

        const uint32_t stb = sb + (c & 3) * STAGE_BYTES;
        const uint32_t aW = stb + (wm * 32) * ROWB;
        const uint32_t bW = stb + OFFB + (wn * 64) * ROWB;

        uint32_t a[2][2][4];
#pragma unroll
        for (int ks = 0; ks < 2; ks++)
#pragma unroll
            for (int mi = 0; mi < 2; mi++)
                ldm_x4(a[ks][mi][0], a[ks][mi][1], a[ks][mi][2], a[ks][mi][3],
                       aW + (mi * 16 + a_row) * ROWB + (ks * 16 + a_k) * 2);

        uint32_t b[3][4];
        ldm_x4(b[0][0], b[0][1], b[0][2], b[0][3], bW + b_n * ROWB + b_k * 2);
        ldm_x4(b[1][0], b[1][1], b[1][2], b[1][3], bW + (16 + b_n) * ROWB + b_k * 2);
#pragma unroll
        for (int i = 0; i < 8; i++) {
            if (i + 2 < 8) {
                const int ks2 = (i + 2) >> 2, nf2 = (i + 2) & 3;
                const int slot = (i + 2) % 3;
                ldm_x4(b[slot][0], b[slot][1], b[slot][2], b[slot][3],
                       bW + (nf2 * 16 + b_n) * ROWB + (ks2 * 16 + b_k) * 2);
            }
            const int ks = i >> 2, nf = i & 3;
            const uint32_t* bb = b[i % 3];
#pragma unroll
            for (int mi = 0; mi < 2; mi++) {
                mma_f16(acc[mi][nf * 2],     a[ks][mi], bb);
                mma_f16(acc[mi][nf * 2 + 1], a[ks][mi], bb + 2);
            }
        }
    }

    const int lrow = l >> 2;
    const int lcol = (l & 3) * 2;
#pragma unroll
    for (int mi = 0; mi < 2; mi++) {
        const int grow = rowBase + wm * 32 + mi * 16 + lrow;
#pragma unroll
        for (int nb = 0; nb < 8; nb++) {
            const int gcol = colBase + wn * 64 + nb * 8 + lcol;
            if (SKIP80 && (gcol & 127) >= 80) continue;
            float v0 = acc[mi][nb][0], v1 = acc[mi][nb][1];
            float v2 = acc[mi][nb][2], v3 = acc[mi][nb][3];
            if (EPI == 2) {
                v0 = softplusf(v0 + bias[gcol]);
                v1 = softplusf(v1 + bias[gcol + 1]);
                v2 = softplusf(v2 + bias[gcol]);
                v3 = softplusf(v3 + bias[gcol + 1]);
                *(__half2*)(CwH + (size_t)grow * ldc + gcol) = __floats2half2_rn(v0, v1);
                *(__half2*)(CwH + (size_t)(grow + 8) * ldc + gcol) = __floats2half2_rn(v2, v3);
            } else if (EPI == 3) {
                *(__half2*)(CwH + (size_t)grow * ldc + gcol) = __floats2half2_rn(v0, v1);
                *(__half2*)(CwH + (size_t)(grow + 8) * ldc + gcol) = __floats2half2_rn(v2, v3);
            } else {
                *(float2*)(Cw + (size_t)grow * ldc + gcol) = make_float2(v0, v1);
                *(float2*)(Cw + (size_t)(grow + 8) * ldc + gcol) = make_float2(v2, v3);
            }
        }
    }
#undef LOAD_STAGE
}

// ---------------- merged operand-prep kernel ----------------
#define SEG0 (BL * KIN / 4)
#define SEG1 (2 * D_INNER * KIN / 4)
#define SEG2 (D_MODEL * KOUT / 4)
#define SEG3 (2 * 80 * D_INNER / 4)
#define SEG4 (2 * D_INNER * DT_RANK / 4)
#define PREP_TOTAL (SEG0 + SEG1 + SEG2 + SEG3 + SEG4)
__global__ void prep_kernel(
    const float* __restrict__ x, const float* __restrict__ in_w,
    const float* __restrict__ out_w,
    const float* __restrict__ xp_f, const float* __restrict__ xp_b,
    const float* __restrict__ dt_f, const float* __restrict__ dt_b,
    __half* __restrict__ ax, __half* __restrict__ wi, __half* __restrict__ wo,
    __half* __restrict__ w3, __half* __restrict__ wdtf, __half* __restrict__ wdtb)
{
    int i4 = blockIdx.x * blockDim.x + threadIdx.x;
    if (i4 >= PREP_TOTAL) return;

    if (i4 < SEG0) {
        const int t = i4 * 4;
        const int r = t / KIN, k = t % KIN;
        const float4 v = *(const float4*)(x + t);
        float vv[4] = {v.x, v.y, v.z, v.w};
        unsigned short hs[4], ls[4];
#pragma unroll
        for (int j = 0; j < 4; j++) split_h(vv[j], hs[j], ls[j]);
        unsigned short* o = (unsigned short*)ax;
        const size_t base = (size_t)r * KIN2 + k;
        *(ushort4*)(o + base) = make_ushort4(hs[0], hs[1], hs[2], hs[3]);
        *(ushort4*)(o + base + KIN) = make_ushort4(ls[0], ls[1], ls[2], ls[3]);
        return;
    }
    i4 -= SEG0;
    if (i4 < SEG1) {
        const int t = i4 * 4;
        const int r = t / KIN, k = t % KIN;
        const float4 v = *(const float4*)(in_w + t);
        float vv[4] = {v.x, v.y, v.z, v.w};
        unsigned short hs[4], ls[4];
#pragma unroll
        for (int j = 0; j < 4; j++) split_h(vv[j], hs[j], ls[j]);
        unsigned short* o = (unsigned short*)wi;
        const size_t base = (size_t)r * KIN2 + k;
        *(ushort4*)(o + base) = make_ushort4(hs[0], hs[1], hs[2], hs[3]);
        *(ushort4*)(o + base + KIN) = make_ushort4(hs[0], hs[1], hs[2], hs[3]);
        return;
    }
    i4 -= SEG1;
    if (i4 < SEG2) {
        const int t = i4 * 4;
        const int r = t / KOUT, k = t % KOUT;
        const float4 v = *(const float4*)(out_w + t);
        float vv[4] = {v.x, v.y, v.z, v.w};
        unsigned short hs[4], ls[4];
#pragma unroll
        for (int j = 0; j < 4; j++) split_h(vv[j], hs[j], ls[j]);
        unsigned short* o = (unsigned short*)wo;
        const size_t base = (size_t)r * KOUT2 + k;
        *(ushort4*)(o + base) = make_ushort4(hs[0], hs[1], hs[2], hs[3]);
        *(ushort4*)(o + base + KOUT) = make_ushort4(hs[0], hs[1], hs[2], hs[3]);
        return;
    }
    i4 -= SEG2;
    if (i4 < SEG3) {
        const int t = i4 * 4;
        const int dir = t / (80 * D_INNER);
        const int rem = t % (80 * D_INNER);
        const int n = rem / D_INNER, k = rem % D_INNER;
        const float* w = dir ? xp_b : xp_f;
        const float4 v = *(const float4*)(w + (size_t)n * D_INNER + k);
        float vv[4] = {v.x, v.y, v.z, v.w};
        unsigned short hs[4], ls[4];
#pragma unroll
        for (int j = 0; j < 4; j++) split_h(vv[j], hs[j], ls[j]);
        unsigned short* o = (unsigned short*)w3;
        const size_t base = (size_t)(dir * 128 + n) * KOUT2 + k;
        *(ushort4*)(o + base) = make_ushort4(hs[0], hs[1], hs[2], hs[3]);
        *(ushort4*)(o + base + D_INNER) = make_ushort4(hs[0], hs[1], hs[2], hs[3]);
        return;
    }
    i4 -= SEG3;
    {
        const int t = i4 * 4;
        const int dir = t / (D_INNER * DT_RANK);
        const int rem = t % (D_INNER * DT_RANK);
        const int n = rem / DT_RANK, k = rem % DT_RANK;
        const float* w = dir ? dt_b : dt_f;
        unsigned short* o = (unsigned short*)(dir ? wdtb : wdtf);
        const float4 v = *(const float4*)(w + (size_t)n * DT_RANK + k);
        float vv[4] = {v.x, v.y, v.z, v.w};
        unsigned short hs[4], ls[4];
#pragma unroll
        for (int j = 0; j < 4; j++) split_h(vv[j], hs[j], ls[j]);
        const size_t base = (size_t)n * (2 * DT_RANK) + k;
        *(ushort4*)(o + base) = make_ushort4(hs[0], hs[1], hs[2], hs[3]);
        *(ushort4*)(o + base + DT_RANK) = make_ushort4(hs[0], hs[1], hs[2], hs[3]);
    }
}

// ---------------- combine x_proj split-K partials (fp16 partials) ----------------
__global__ void dbc48_combine_kernel(const __half* __restrict__ parts,
                                     __half* __restrict__ d48f,
                                     __half* __restrict__ d48b,
                                     float* __restrict__ dbc_bc)
{
    const int i4 = blockIdx.x * blockDim.x + threadIdx.x;
    if (i4 * 4 >= BL * 160) return;
    const int t = i4 * 4;
    const int row = t / 160;
    const int rr = t % 160;
    const int dir = rr / 80;
    const int c = rr % 80;
    const size_t src = (size_t)row * DBC_PAD + dir * 128 + c;
    float vv[4] = {0.f, 0.f, 0.f, 0.f};
#pragma unroll
    for (int p = 0; p < XPROJ_SPLITK; p++) {
        const ushort4 v = *(const ushort4*)((const unsigned short*)parts
                                            + (size_t)p * (BL * DBC_PAD) + src);
        vv[0] += __half2float(__ushort_as_half(v.x));
        vv[1] += __half2float(__ushort_as_half(v.y));
        vv[2] += __half2float(__ushort_as_half(v.z));
        vv[3] += __half2float(__ushort_as_half(v.w));
    }
    if (c < DT_RANK) {
        unsigned short hs[4], ls[4];
#pragma unroll
        for (int j = 0; j < 4; j++) split_h(vv[j], hs[j], ls[j]);
        unsigned short* o = (unsigned short*)(dir ? d48b : d48f);
        const size_t base = (size_t)row * (2 * DT_RANK) + c;
        *(ushort4*)(o + base) = make_ushort4(hs[0], hs[1], hs[2], hs[3]);
        *(ushort4*)(o + base + DT_RANK) = make_ushort4(ls[0], ls[1], ls[2], ls[3]);
    } else {
        *(float4*)(dbc_bc + (size_t)row * 64 + dir * 32 + (c - DT_RANK)) =
            make_float4(vv[0], vv[1], vv[2], vv[3]);
    }
}

// ---------------- causal conv(4) + SiLU -> xsc16; silu(z) -> fp16 ----------------
__global__ void conv_silu_kernel(
    const __half* __restrict__ inp,
    const float* __restrict__ cw, const float* __restrict__ cb,
    __half* __restrict__ zs, __half* __restrict__ xsc16)
{
    const int idx = blockIdx.x * blockDim.x + threadIdx.x;
    if (idx >= BL * D_INNER) return;
    const int e = idx % D_INNER;
    const int row = idx / D_INNER;
    const int l = row & (SEQ - 1);
    const float w0 = cw[e * 4 + 0];
    const float w1 = cw[e * 4 + 1];
    const float w2 = cw[e * 4 + 2];
    const float w3 = cw[e * 4 + 3];
    const size_t base = (size_t)row * (2 * D_INNER) + e;
    float acc = cb[e];
    acc = fmaf(w3, __half2float(inp[base]), acc);
    if (l >= 1) acc = fmaf(w2, __half2float(inp[base - 2 * D_INNER]), acc);
    if (l >= 2) acc = fmaf(w1, __half2float(inp[base - 4 * D_INNER]), acc);
    if (l >= 3) acc = fmaf(w0, __half2float(inp[base - 6 * D_INNER]), acc);
    const float xs = siluf(acc);
    unsigned short hi, lo;
    split_h(xs, hi, lo);
    unsigned short* o = (unsigned short*)xsc16 + (size_t)row * KOUT2 + e;
    o[0] = hi;
    o[D_INNER] = lo;
    const float z = __half2float(inp[base + D_INNER]);
    zs[idx] = __float2half_rn(siluf(z));
}

// ---------------- selective scan: 2 states/thread, 3-shfl reduction ----------------
__global__ void __launch_bounds__(256) scan_kernel(
    const __half* __restrict__ delta_f, const __half* __restrict__ delta_b,
    const float* __restrict__ dbc_bc,
    const float* __restrict__ A_log,  const float* __restrict__ A_b_log,
    const __half* __restrict__ xsc16,
    __half* __restrict__ y_f, __half* __restrict__ y_b)
{
    const int dir = blockIdx.z;
    const int b = blockIdx.y;
    const int e0 = blockIdx.x * 32;
    const int t = threadIdx.x;
    const int el = t >> 3;
    const int q = t & 7;
    const int e = e0 + el;
    const __half* delta = dir ? delta_b : delta_f;
    const float* Alog = dir ? A_b_log : A_log;
    __half* y = dir ? y_b : y_f;
    const float An0 = -__expf(Alog[e * D_STATE + q]);
    const float An1 = -__expf(Alog[e * D_STATE + q + 8]);

    __shared__ float s_d[16 * 32];
    __shared__ float s_x[16 * 32];
    __shared__ float s_bc[16 * 32];
    __shared__ float s_y[16 * 32];

    const int lj = t >> 5;
    const int lc = t & 31;
    float h0 = 0.f, h1 = 0.f;
    const size_t rowb = (size_t)b * SEQ;

    for (int c = 0; c < SEQ / 16; c++) {
#pragma unroll
        for (int rr = 0; rr < 2; rr++) {
            const int ljj = lj + rr * 8;
            const int i = c * 16 + ljj;
            const int l = dir ? (SEQ - 1 - i) : i;
            const size_t row = rowb + l;
            s_d[ljj * 32 + lc] = __half2float(delta[row * D_INNER + e0 + lc]);
            const __half xh = xsc16[row * KOUT2 + e0 + lc];
            const __half xl = xsc16[row * KOUT2 + D_INNER + e0 + lc];
            s_x[ljj * 32 + lc] = __half2float(xh) + __half2float(xl);
            s_bc[ljj * 32 + lc] = dbc_bc[row * 64 + dir * 32 + lc];
        }
        __syncthreads();

#pragma unroll
        for (int j = 0; j < 16; j++) {
            const float dlt = s_d[j * 32 + el];
            const float xv  = s_x[j * 32 + el];
            const float Bv0 = s_bc[j * 32 + q];
            const float Bv1 = s_bc[j * 32 + q + 8];
            const float Cv0 = s_bc[j * 32 + 16 + q];
            const float Cv1 = s_bc[j * 32 + 24 + q];
            const float dA0 = __expf(dlt * An0);
            const float dA1 = __expf(dlt * An1);
            const float dx = dlt * xv;
            h0 = fmaf(dA0, h0, dx * Bv0);
            h1 = fmaf(dA1, h1, dx * Bv1);
            float p = fmaf(h0, Cv0, h1 * Cv1);
            p += __shfl_xor_sync(0xffffffffu, p, 4);
            p += __shfl_xor_sync(0xffffffffu, p, 2);
            p += __shfl_xor_sync(0xffffffffu, p, 1);
            if (q == 0) s_y[j * 32 + el] = p;
        }
        __syncthreads();

#pragma unroll
        for (int rr = 0; rr < 2; rr++) {
            const int ljj = lj + rr * 8;
            const int i = c * 16 + ljj;
            const int l = dir ? (SEQ - 1 - i) : i;
            y[(rowb + l) * D_INNER + e0 + lc] = __float2half_rn(s_y[ljj * 32 + lc]);
        }
    }
}

// ---------------- fuse: u = (y_f + y_b + (D+D_b)*xs)*silu(z) -> fp16 pair ----------------
__global__ void fuse_kernel(
    const __half* __restrict__ yf, const __half* __restrict__ yb,
    const __half* __restrict__ xsc16, const __half* __restrict__ zs,
    const float* __restrict__ D1, const float* __restrict__ D2,
    __half* __restrict__ u2)
{
    const int idx4 = blockIdx.x * blockDim.x + threadIdx.x;
    if (idx4 >= (BL * D_INNER) / 4) return;
    const int e4 = (idx4 * 4) % D_INNER;
    const int r = (idx4 * 4) / D_INNER;
    const ushort4 av = *(const ushort4*)((const unsigned short*)yf + (size_t)idx4 * 4);
    const ushort4 bv = *(const ushort4*)((const unsigned short*)yb + (size_t)idx4 * 4);
    const ushort4 zv = *(const ushort4*)((const unsigned short*)zs + (size_t)idx4 * 4);
    const float4 d1 = *(const float4*)(D1 + e4);
    const float4 d2 = *(const float4*)(D2 + e4);
    const ushort4 xh = *(const ushort4*)((const unsigned short*)xsc16 + (size_t)r * KOUT2 + e4);
    const ushort4 xl = *(const ushort4*)((const unsigned short*)xsc16 + (size_t)r * KOUT2 + KOUT + e4);
    float xv[4];
    xv[0] = __half2float(__ushort_as_half(xh.x)) + __half2float(__ushort_as_half(xl.x));
    xv[1] = __half2float(__ushort_as_half(xh.y)) + __half2float(__ushort_as_half(xl.y));
    xv[2] = __half2float(__ushort_as_half(xh.z)) + __half2float(__ushort_as_half(xl.z));
    xv[3] = __half2float(__ushort_as_half(xh.w)) + __half2float(__ushort_as_half(xl.w));
    float ya[4], yb4[4], zf[4];
    ya[0] = __half2float(__ushort_as_half(av.x)); yb4[0] = __half2float(__ushort_as_half(bv.x));
    ya[1] = __half2float(__ushort_as_half(av.y)); yb4[1] = __half2float(__ushort_as_half(bv.y));
    ya[2] = __half2float(__ushort_as_half(av.z)); yb4[2] = __half2float(__ushort_as_half(bv.z));
    ya[3] = __half2float(__ushort_as_half(av.w)); yb4[3] = __half2float(__ushort_as_half(bv.w));
    zf[0] = __half2float(__ushort_as_half(zv.x));
    zf[1] = __half2float(__ushort_as_half(zv.y));
    zf[2] = __half2float(__ushort_as_half(zv.z));
    zf[3] = __half2float(__ushort_as_half(zv.w));
    float vv[4];
    vv[0] = (ya[0] + yb4[0] + (d1.x + d2.x) * xv[0]) * zf[0];
    vv[1] = (ya[1] + yb4[1] + (d1.y + d2.y) * xv[1]) * zf[1];
    vv[2] = (ya[2] + yb4[2] + (d1.z + d2.z) * xv[2]) * zf[2];
    vv[3] = (ya[3] + yb4[3] + (d1.w + d2.w) * xv[3]) * zf[3];
    unsigned short hs[4], ls[4];
#pragma unroll
    for (int j = 0; j < 4; j++) split_h(vv[j], hs[j], ls[j]);
    const size_t base = (size_t)r * KOUT2 + e4;
    *(ushort4*)((unsigned short*)u2 + base) = make_ushort4(hs[0], hs[1], hs[2], hs[3]);
    *(ushort4*)((unsigned short*)u2 + base + KOUT) = make_ushort4(ls[0], ls[1], ls[2], ls[3]);
}

// ---------------- out = sum of 3 out_proj slices (fp16 slices -> fp32 out) ----------------
__global__ void addout3_kernel(float* __restrict__ out, const __half* __restrict__ parts)
{
    const int i4 = blockIdx.x * blockDim.x + threadIdx.x;
    if (i4 * 4 >= BL * D_MODEL) return;
    const unsigned short* p = (const unsigned short*)parts;
    const ushort4 a = *(const ushort4*)(p + (size_t)i4 * 4);
    const ushort4 b = *(const ushort4*)(p + (size_t)(BL * D_MODEL) + i4 * 4);
    const ushort4 c = *(const ushort4*)(p + (size_t)(2 * BL * D_MODEL) + i4 * 4);
    float4 r;
    r.x = __half2float(__ushort_as_half(a.x)) + __half2float(__ushort_as_half(b.x))
        + __half2float(__ushort_as_half(c.x));
    r.y = __half2float(__ushort_as_half(a.y)) + __half2float(__ushort_as_half(b.y))
        + __half2float(__ushort_as_half(c.y));
    r.z = __half2float(__ushort_as_half(a.z)) + __half2float(__ushort_as_half(b.z))
        + __half2float(__ushort_as_half(c.z));
    r.w = __half2float(__ushort_as_half(a.w)) + __half2float(__ushort_as_half(b.w))
        + __half2float(__ushort_as_half(c.w));
    *(float4*)(out + (size_t)i4 * 4) = r;
}

// ---------------- launcher ----------------
extern "C" void kernel_launch(void* const* d_in, const int* in_sizes, int n_in,
                              void* d_out, int out_size)
{
    const float* x          = (const float*)d_in[0];
    const float* in_proj_w  = (const float*)d_in[1];
    const float* conv_w     = (const float*)d_in[2];
    const float* conv_bias  = (const float*)d_in[3];
    const float* x_proj_w   = (const float*)d_in[4];
    const float* dt_proj_w  = (const float*)d_in[5];
    const float* dt_proj_b  = (const float*)d_in[6];
    const float* A_log      = (const float*)d_in[7];
    const float* D_param    = (const float*)d_in[8];
    const float* out_proj_w = (const float*)d_in[9];
    const float* A_b_log    = (const float*)d_in[10];
    const float* x_proj_b_w = (const float*)d_in[11];
    const float* dt_proj_b_w= (const float*)d_in[12];
    const float* dt_proj_b_b= (const float*)d_in[13];
    const float* D_b        = (const float*)d_in[14];
    float* out = (float*)d_out;

    float *p_dbc_bc;
    __half *p_inp, *p_dbcp, *p_opart;
    __half *p_zs, *p_y_f, *p_y_b;
    __half *p_delta_f, *p_delta_b;
    __half *p_ax, *p_wi, *p_xsc16, *p_w3, *p_wdtf, *p_wdtb, *p_d48f, *p_d48b, *p_u2, *p_wo;
    cudaGetSymbolAddress((void**)&p_inp, g_inp);
    cudaGetSymbolAddress((void**)&p_zs, g_zs);
    cudaGetSymbolAddress((void**)&p_dbcp, g_dbcp);
    cudaGetSymbolAddress((void**)&p_dbc_bc, g_dbc_bc);
    cudaGetSymbolAddress((void**)&p_delta_f, g_delta_f);
    cudaGetSymbolAddress((void**)&p_delta_b, g_delta_b);
    cudaGetSymbolAddress((void**)&p_y_f, g_y_f);
    cudaGetSymbolAddress((void**)&p_y_b, g_y_b);
    cudaGetSymbolAddress((void**)&p_opart, g_opart);
    cudaGetSymbolAddress((void**)&p_ax, g_ax);
    cudaGetSymbolAddress((void**)&p_wi, g_wi);
    cudaGetSymbolAddress((void**)&p_xsc16, g_xsc16);
    cudaGetSymbolAddress((void**)&p_w3, g_w3);
    cudaGetSymbolAddress((void**)&p_wdtf, g_wdt_f);
    cudaGetSymbolAddress((void**)&p_wdtb, g_wdt_b);
    cudaGetSymbolAddress((void**)&p_d48f, g_dbc48_f);
    cudaGetSymbolAddress((void**)&p_d48b, g_dbc48_b);
    cudaGetSymbolAddress((void**)&p_u2, g_u2);
    cudaGetSymbolAddress((void**)&p_wo, g_wo);

    const int SMEM_MMA = 4 * STAGE_BYTES; // 81920
    cudaFuncSetAttribute((const void*)hmma_f16_nt<3, 0, 0>,
                         cudaFuncAttributeMaxDynamicSharedMemorySize, SMEM_MMA);
    cudaFuncSetAttribute((const void*)hmma_f16_nt<3, 0, 1>,
                         cudaFuncAttributeMaxDynamicSharedMemorySize, SMEM_MMA);
    cudaFuncSetAttribute((const void*)hmma_f16_nt<2, 1, 0>,
                         cudaFuncAttributeMaxDynamicSharedMemorySize, SMEM_MMA);

    // 0) all operand splits in one launch
    prep_kernel<<<(PREP_TOTAL + 255) / 256, 256>>>(
        x, in_proj_w, out_proj_w, x_proj_w, x_proj_b_w, dt_proj_w, dt_proj_b_w,
        p_ax, p_wi, p_wo, p_w3, p_wdtf, p_wdtb);

    // 1) xz = x @ in_proj_w^T -> fp16
    hmma_f16_nt<3, 0, 0><<<dim3((2 * D_INNER) / 128, BL / 128, 1), 256, SMEM_MMA>>>(
        (const __half*)p_ax, p_wi, (float*)p_inp, 2 * D_INNER, KIN2, KIN2 / 32, 0,
        nullptr, nullptr, nullptr, nullptr, nullptr);

    // 2) causal conv + silu -> xsc16; silu(z) -> fp16
    conv_silu_kernel<<<(BL * D_INNER + 255) / 256, 256>>>(
        p_inp, conv_w, conv_bias, p_zs, p_xsc16);

    // 3) x_proj both dirs (padded N=256, split-K=8, fp16 partials, padding skipped)
    hmma_f16_nt<3, 0, 1><<<dim3(DBC_PAD / 128, BL / 128, XPROJ_SPLITK), 256, SMEM_MMA>>>(
        p_xsc16, p_w3, (float*)p_dbcp, DBC_PAD, KOUT2, KOUT2 / 32 / XPROJ_SPLITK,
        (long long)BL * DBC_PAD, nullptr, nullptr, nullptr, nullptr, nullptr);

    // 4) combine partial strips -> d48 fp16 + compact B/C
    dbc48_combine_kernel<<<(BL * 160 / 4 + 255) / 256, 256>>>(
        p_dbcp, p_d48f, p_d48b, p_dbc_bc);

    // 5) delta_{f,b} = softplus(d48 @ wdt^T + bias) -> fp16
    hmma_f16_nt<2, 1, 0><<<dim3(D_INNER / 128, BL / 128, 2), 256, SMEM_MMA>>>(
        p_d48f, p_wdtf, (float*)p_delta_f, D_INNER, 2 * DT_RANK, (2 * DT_RANK) / 32, 0,
        dt_proj_b, p_d48b, p_wdtb, (float*)p_delta_b, dt_proj_b_b);

    // 6) selective scan -> y fp16
    scan_kernel<<<dim3(D_INNER / 32, NB, 2), 256>>>(
        p_delta_f, p_delta_b, p_dbc_bc, A_log, A_b_log, p_xsc16, p_y_f, p_y_b);

    // 7) fuse -> u fp16 pair
    fuse_kernel<<<(BL * D_INNER / 4 + 255) / 256, 256>>>(
        p_y_f, p_y_b, p_xsc16, p_zs, D_param, D_b, p_u2);

    // 8) out slices = u @ out_proj_w^T (split-K=3, fp16 slices)
    hmma_f16_nt<3, 0, 0><<<dim3(D_MODEL / 128, BL / 128, 3), 256, SMEM_MMA>>>(
        p_u2, p_wo, (float*)p_opart, D_MODEL, KOUT2, KOUT2 / 32 / 3,
        (long long)BL * D_MODEL, nullptr, nullptr, nullptr, nullptr, nullptr);
    addout3_kernel<<<(BL * D_MODEL / 4 + 255) / 256, 256>>>(out, p_opart);
}

// round 15
// speedup vs baseline: 1.0473x; 1.0473x over previous
#include <cuda_runtime.h>
#include <cuda_fp16.h>
#include <cstdint>
#include <cstddef>

// ---------------- problem constants ----------------
#define D_MODEL 768
#define D_INNER 1536
#define D_STATE 16
#define DT_RANK 48
#define NB 2
#define SEQ 1024
#define BL (NB * SEQ)                 // 2048
#define KIN  D_MODEL                  // 768
#define KIN2 (2 * KIN)                // 1536
#define KOUT D_INNER                  // 1536
#define KOUT2 (2 * KOUT)              // 3072
#define DBC_PAD 256
#define XPROJ_SPLITK 8

// ---------------- scratch (static __device__ arrays; zero-initialized) ----------------
__device__ float g_inp[BL * D_INNER];               // in_proj xs-half (fp32)
__device__ __half g_zs[BL * D_INNER];               // silu(z), written by GEMM epilogue
__device__ float g_dbcp[XPROJ_SPLITK * BL * DBC_PAD];
__device__ float g_dbc_bc[BL * 64];
__device__ __half g_delta_f[BL * D_INNER];
__device__ __half g_delta_b[BL * D_INNER];
__device__ __half g_y_f[BL * D_INNER];
__device__ __half g_y_b[BL * D_INNER];
__device__ float g_opart[3 * BL * D_MODEL];
__device__ __half g_ax[BL * KIN2];                  // x split (hi|lo)
__device__ __half g_axh[BL * KIN];                  // x hi only
__device__ __half g_wi[D_INNER * KIN2];             // in_proj_w rows 0..1535 (hi|hi)
__device__ __half g_wiz[D_INNER * KIN];             // in_proj_w rows 1536..3071 (hi)
__device__ __half g_xsc16[BL * KOUT2];
__device__ __half g_w3[DBC_PAD * KOUT2];
__device__ __half g_wdt_f[D_INNER * 2 * DT_RANK];
__device__ __half g_wdt_b[D_INNER * 2 * DT_RANK];
__device__ __half g_dbc48_f[BL * 2 * DT_RANK];
__device__ __half g_dbc48_b[BL * 2 * DT_RANK];
__device__ __half g_u2[BL * KOUT2];
__device__ __half g_wo[D_MODEL * KOUT2];

// ---------------- math helpers ----------------
__device__ __forceinline__ float siluf(float x) { return x / (1.f + __expf(-x)); }
__device__ __forceinline__ float softplusf(float x) {
    return (x > 20.f) ? x : log1pf(__expf(x));
}
__device__ __forceinline__ uint32_t smem_u32(const void* p) {
    uint32_t a;
    asm("{ .reg .u64 t; cvta.to.shared.u64 t, %1; cvt.u32.u64 %0, t; }" : "=r"(a) : "l"(p));
    return a;
}
__device__ __forceinline__ void cp_async16(uint32_t saddr, const void* g) {
    asm volatile("cp.async.cg.shared.global [%0], [%1], 16;" :: "r"(saddr), "l"(g));
}
__device__ __forceinline__ void cp_commit() {
    asm volatile("cp.async.commit_group;" ::: "memory");
}
__device__ __forceinline__ void ldm_x4(uint32_t& r0, uint32_t& r1, uint32_t& r2,
                                       uint32_t& r3, uint32_t addr) {
    asm volatile("ldmatrix.sync.aligned.m8n8.x4.shared.b16 {%0,%1,%2,%3}, [%4];"
                 : "=r"(r0), "=r"(r1), "=r"(r2), "=r"(r3) : "r"(addr));
}
__device__ __forceinline__ void mma_f16(float* c, const uint32_t* a, const uint32_t* b) {
    asm volatile(
        "mma.sync.aligned.m16n8k16.row.col.f32.f16.f16.f32 "
        "{%0,%1,%2,%3}, {%4,%5,%6,%7}, {%8,%9}, {%0,%1,%2,%3};"
        : "+f"(c[0]), "+f"(c[1]), "+f"(c[2]), "+f"(c[3])
        : "r"(a[0]), "r"(a[1]), "r"(a[2]), "r"(a[3]), "r"(b[0]), "r"(b[1]));
}
__device__ __forceinline__ void split_h(float v, unsigned short& hi, unsigned short& lo) {
    __half h = __float2half_rn(v);
    __half l = __float2half_rn(v - __half2float(h));
    hi = __half_as_ushort(h); lo = __half_as_ushort(l);
}

// ---------------- HMMA fp16 GEMM ----------------
// EPI: 0 = fp32 store, 2 = softplus(v+bias)->half.
// ZMODE: 0 = split-K slices; 1 = two problems (shared Kp);
//        2 = mixed: z=0 -> fp32 C, z=1 -> (A2,B2,Kp2,nChunks2) with silu->half into C2.
// SKIP80: skip stores where (gcol & 127) >= 80.
#define ROWB 80
#define STAGE_BYTES 20480
#define OFFB 10240
template <int EPI, int ZMODE, int SKIP80>
__global__ void __launch_bounds__(256) hmma_f16_nt(
    const __half* __restrict__ A,
    const __half* __restrict__ B,
    float* __restrict__ C, int ldc, int Kp, int nChunks, long long zstride,
    const float* __restrict__ bias,
    const __half* __restrict__ A2, const __half* __restrict__ B2,
    float* __restrict__ C2, const float* __restrict__ bias2,
    int Kp2, int nChunks2)
{
    extern __shared__ char smem[];
    const uint32_t sb = smem_u32(smem);
    const int tid = threadIdx.x;
    const int rowBase = blockIdx.y * 128;
    const int colBase = blockIdx.x * 128;
    float* Cw = nullptr;
    __half* CwH = nullptr;
    int chunkBase = 0;
    bool zsilu = false;
    if (ZMODE == 1) {
        if (blockIdx.z == 1) { A = A2; B = B2; C = C2; bias = bias2; }
        if (EPI == 2) CwH = (__half*)C; else Cw = C;
    } else if (ZMODE == 2) {
        if (blockIdx.z == 0) {
            Cw = C;
        } else {
            A = A2; B = B2; Kp = Kp2; nChunks = nChunks2;
            CwH = (__half*)C2; zsilu = true;
        }
    } else {
        Cw = C + (size_t)blockIdx.z * (size_t)zstride;
        chunkBase = blockIdx.z * nChunks;
    }

    const int r0 = tid >> 2, c0 = tid & 3;
    const int r1 = (tid + 256) >> 2, c1 = (tid + 256) & 3;
    const char* gA0 = (const char*)(A + (size_t)(rowBase + r0) * Kp + c0 * 8)
                      + (size_t)chunkBase * 64;
    const char* gA1 = (const char*)(A + (size_t)(rowBase + r1) * Kp + c1 * 8)
                      + (size_t)chunkBase * 64;
    const char* gB0 = (const char*)(B + (size_t)(colBase + r0) * Kp + c0 * 8)
                      + (size_t)chunkBase * 64;
    const char* gB1 = (const char*)(B + (size_t)(colBase + r1) * Kp + c1 * 8)
                      + (size_t)chunkBase * 64;
    const uint32_t sA0 = r0 * ROWB + c0 * 16, sA1 = r1 * ROWB + c1 * 16;
    const uint32_t sB0 = OFFB + sA0, sB1 = OFFB + sA1;

#define LOAD_STAGE(c) do {                                                  \
    const uint32_t _base = sb + ((c) & 3) * STAGE_BYTES;                    \
    const size_t _gk = (size_t)(c) * 64;                                    \
    cp_async16(_base + sA0, gA0 + _gk);                                     \
    cp_async16(_base + sA1, gA1 + _gk);                                     \
    cp_async16(_base + sB0, gB0 + _gk);                                     \
    cp_async16(_base + sB1, gB1 + _gk);                                     \
} while (0)

    const int wid = tid >> 5;
    const int l = tid & 31;
    const int wm = wid & 3;
    const int wn = wid >> 2;
    const int a_row = ((l >> 3) & 1) * 8 + (l & 7);
    const int a_k   = (l >> 4) * 8;
    const int b_n   = (l >> 4) * 8 + (l & 7);
    const int b_k   = ((l >> 3) & 1) * 8;

    float acc[2][8][4];
#pragma unroll
    for (int i = 0; i < 2; i++)
#pragma unroll
        for (int j = 0; j < 8; j++)
#pragma unroll
            for (int q = 0; q < 4; q++) acc[i][j][q] = 0.f;

    LOAD_STAGE(0); cp_commit();
    if (nChunks > 1) LOAD_STAGE(1);
    cp_commit();
    if (nChunks > 2) LOAD_STAGE(2);
    cp_commit();

    for (int c = 0; c < nChunks; c++) {
        asm volatile("cp.async.wait_group 2;" ::: "memory");
        __syncthreads();
        if (c + 3 < nChunks) LOAD_STAGE(c + 3);
        cp_commit();

        const uint32_t stb = sb + (c & 3) * STAGE_BYTES;
        const uint32_t aW = stb + (wm * 32) * ROWB;
        const uint32_t bW = stb + OFFB + (wn * 64) * ROWB;

        uint32_t a[2][2][4];
#pragma unroll
        for (int ks = 0; ks < 2; ks++)
#pragma unroll
            for (int mi = 0; mi < 2; mi++)
                ldm_x4(a[ks][mi][0], a[ks][mi][1], a[ks][mi][2], a[ks][mi][3],
                       aW + (mi * 16 + a_row) * ROWB + (ks * 16 + a_k) * 2);

        uint32_t b[3][4];
        ldm_x4(b[0][0], b[0][1], b[0][2], b[0][3], bW + b_n * ROWB + b_k * 2);
        ldm_x4(b[1][0], b[1][1], b[1][2], b[1][3], bW + (16 + b_n) * ROWB + b_k * 2);
#pragma unroll
        for (int i = 0; i < 8; i++) {
            if (i + 2 < 8) {
                const int ks2 = (i + 2) >> 2, nf2 = (i + 2) & 3;
                const int slot = (i + 2) % 3;
                ldm_x4(b[slot][0], b[slot][1], b[slot][2], b[slot][3],
                       bW + (nf2 * 16 + b_n) * ROWB + (ks2 * 16 + b_k) * 2);
            }
            const int ks = i >> 2, nf = i & 3;
            const uint32_t* bb = b[i % 3];
#pragma unroll
            for (int mi = 0; mi < 2; mi++) {
                mma_f16(acc[mi][nf * 2],     a[ks][mi], bb);
                mma_f16(acc[mi][nf * 2 + 1], a[ks][mi], bb + 2);
            }
        }
    }

    const int lrow = l >> 2;
    const int lcol = (l & 3) * 2;
#pragma unroll
    for (int mi = 0; mi < 2; mi++) {
        const int grow = rowBase + wm * 32 + mi * 16 + lrow;
#pragma unroll
        for (int nb = 0; nb < 8; nb++) {
            const int gcol = colBase + wn * 64 + nb * 8 + lcol;
            if (SKIP80 && (gcol & 127) >= 80) continue;
            float v0 = acc[mi][nb][0], v1 = acc[mi][nb][1];
            float v2 = acc[mi][nb][2], v3 = acc[mi][nb][3];
            if (ZMODE == 2 && zsilu) {
                *(__half2*)(CwH + (size_t)grow * ldc + gcol) =
                    __floats2half2_rn(siluf(v0), siluf(v1));
                *(__half2*)(CwH + (size_t)(grow + 8) * ldc + gcol) =
                    __floats2half2_rn(siluf(v2), siluf(v3));
            } else if (EPI == 2) {
                v0 = softplusf(v0 + bias[gcol]);
                v1 = softplusf(v1 + bias[gcol + 1]);
                v2 = softplusf(v2 + bias[gcol]);
                v3 = softplusf(v3 + bias[gcol + 1]);
                *(__half2*)(CwH + (size_t)grow * ldc + gcol) = __floats2half2_rn(v0, v1);
                *(__half2*)(CwH + (size_t)(grow + 8) * ldc + gcol) = __floats2half2_rn(v2, v3);
            } else {
                *(float2*)(Cw + (size_t)grow * ldc + gcol) = make_float2(v0, v1);
                *(float2*)(Cw + (size_t)(grow + 8) * ldc + gcol) = make_float2(v2, v3);
            }
        }
    }
#undef LOAD_STAGE
}

// ---------------- merged operand-prep kernel ----------------
#define SEG0 (BL * KIN / 4)                 // x -> ax (hi|lo) + axh (hi)
#define SEG1 (2 * D_INNER * KIN / 4)        // in_proj_w -> wi (hi|hi) / wiz (hi)
#define SEG2 (D_MODEL * KOUT / 4)           // out_proj_w -> wo (hi|hi)
#define SEG3 (2 * 80 * D_INNER / 4)         // x_proj -> w3 padded (hi|hi)
#define SEG4 (2 * D_INNER * DT_RANK / 4)    // dt_proj -> wdt (hi|hi)
#define PREP_TOTAL (SEG0 + SEG1 + SEG2 + SEG3 + SEG4)
__global__ void prep_kernel(
    const float* __restrict__ x, const float* __restrict__ in_w,
    const float* __restrict__ out_w,
    const float* __restrict__ xp_f, const float* __restrict__ xp_b,
    const float* __restrict__ dt_f, const float* __restrict__ dt_b,
    __half* __restrict__ ax, __half* __restrict__ axh,
    __half* __restrict__ wi, __half* __restrict__ wiz,
    __half* __restrict__ wo,
    __half* __restrict__ w3, __half* __restrict__ wdtf, __half* __restrict__ wdtb)
{
    int i4 = blockIdx.x * blockDim.x + threadIdx.x;
    if (i4 >= PREP_TOTAL) return;

    if (i4 < SEG0) {
        const int t = i4 * 4;
        const int r = t / KIN, k = t % KIN;
        const float4 v = *(const float4*)(x + t);
        float vv[4] = {v.x, v.y, v.z, v.w};
        unsigned short hs[4], ls[4];
#pragma unroll
        for (int j = 0; j < 4; j++) split_h(vv[j], hs[j], ls[j]);
        unsigned short* o = (unsigned short*)ax;
        const size_t base = (size_t)r * KIN2 + k;
        *(ushort4*)(o + base) = make_ushort4(hs[0], hs[1], hs[2], hs[3]);
        *(ushort4*)(o + base + KIN) = make_ushort4(ls[0], ls[1], ls[2], ls[3]);
        *(ushort4*)((unsigned short*)axh + t) = make_ushort4(hs[0], hs[1], hs[2], hs[3]);
        return;
    }
    i4 -= SEG0;
    if (i4 < SEG1) {
        const int t = i4 * 4;
        const int r = t / KIN, k = t % KIN;
        const float4 v = *(const float4*)(in_w + t);
        float vv[4] = {v.x, v.y, v.z, v.w};
        unsigned short hs[4], ls[4];
#pragma unroll
        for (int j = 0; j < 4; j++) split_h(vv[j], hs[j], ls[j]);
        const ushort4 H = make_ushort4(hs[0], hs[1], hs[2], hs[3]);
        if (r < D_INNER) {
            unsigned short* o = (unsigned short*)wi;
            const size_t base = (size_t)r * KIN2 + k;
            *(ushort4*)(o + base) = H;
            *(ushort4*)(o + base + KIN) = H;
        } else {
            unsigned short* o = (unsigned short*)wiz;
            *(ushort4*)(o + (size_t)(r - D_INNER) * KIN + k) = H;
        }
        return;
    }
    i4 -= SEG1;
    if (i4 < SEG2) {
        const int t = i4 * 4;
        const int r = t / KOUT, k = t % KOUT;
        const float4 v = *(const float4*)(out_w + t);
        float vv[4] = {v.x, v.y, v.z, v.w};
        unsigned short hs[4], ls[4];
#pragma unroll
        for (int j = 0; j < 4; j++) split_h(vv[j], hs[j], ls[j]);
        unsigned short* o = (unsigned short*)wo;
        const size_t base = (size_t)r * KOUT2 + k;
        *(ushort4*)(o + base) = make_ushort4(hs[0], hs[1], hs[2], hs[3]);
        *(ushort4*)(o + base + KOUT) = make_ushort4(hs[0], hs[1], hs[2], hs[3]);
        return;
    }
    i4 -= SEG2;
    if (i4 < SEG3) {
        const int t = i4 * 4;
        const int dir = t / (80 * D_INNER);
        const int rem = t % (80 * D_INNER);
        const int n = rem / D_INNER, k = rem % D_INNER;
        const float* w = dir ? xp_b : xp_f;
        const float4 v = *(const float4*)(w + (size_t)n * D_INNER + k);
        float vv[4] = {v.x, v.y, v.z, v.w};
        unsigned short hs[4], ls[4];
#pragma unroll
        for (int j = 0; j < 4; j++) split_h(vv[j], hs[j], ls[j]);
        unsigned short* o = (unsigned short*)w3;
        const size_t base = (size_t)(dir * 128 + n) * KOUT2 + k;
        *(ushort4*)(o + base) = make_ushort4(hs[0], hs[1], hs[2], hs[3]);
        *(ushort4*)(o + base + D_INNER) = make_ushort4(hs[0], hs[1], hs[2], hs[3]);
        return;
    }
    i4 -= SEG3;
    {
        const int t = i4 * 4;
        const int dir = t / (D_INNER * DT_RANK);
        const int rem = t % (D_INNER * DT_RANK);
        const int n = rem / DT_RANK, k = rem % DT_RANK;
        const float* w = dir ? dt_b : dt_f;
        unsigned short* o = (unsigned short*)(dir ? wdtb : wdtf);
        const float4 v = *(const float4*)(w + (size_t)n * DT_RANK + k);
        float vv[4] = {v.x, v.y, v.z, v.w};
        unsigned short hs[4], ls[4];
#pragma unroll
        for (int j = 0; j < 4; j++) split_h(vv[j], hs[j], ls[j]);
        const size_t base = (size_t)n * (2 * DT_RANK) + k;
        *(ushort4*)(o + base) = make_ushort4(hs[0], hs[1], hs[2], hs[3]);
        *(ushort4*)(o + base + DT_RANK) = make_ushort4(hs[0], hs[1], hs[2], hs[3]);
    }
}

// ---------------- combine x_proj split-K partials (fp32 partials) ----------------
__global__ void dbc48_combine_kernel(const float* __restrict__ parts,
                                     __half* __restrict__ d48f,
                                     __half* __restrict__ d48b,
                                     float* __restrict__ dbc_bc)
{
    const int i4 = blockIdx.x * blockDim.x + threadIdx.x;
    if (i4 * 4 >= BL * 160) return;
    const int t = i4 * 4;
    const int row = t / 160;
    const int rr = t % 160;
    const int dir = rr / 80;
    const int c = rr % 80;
    const size_t src = (size_t)row * DBC_PAD + dir * 128 + c;
    float vv[4] = {0.f, 0.f, 0.f, 0.f};
#pragma unroll
    for (int p = 0; p < XPROJ_SPLITK; p++) {
        const float4 v = *(const float4*)(parts + (size_t)p * (BL * DBC_PAD) + src);
        vv[0] += v.x; vv[1] += v.y; vv[2] += v.z; vv[3] += v.w;
    }
    if (c < DT_RANK) {
        unsigned short hs[4], ls[4];
#pragma unroll
        for (int j = 0; j < 4; j++) split_h(vv[j], hs[j], ls[j]);
        unsigned short* o = (unsigned short*)(dir ? d48b : d48f);
        const size_t base = (size_t)row * (2 * DT_RANK) + c;
        *(ushort4*)(o + base) = make_ushort4(hs[0], hs[1], hs[2], hs[3]);
        *(ushort4*)(o + base + DT_RANK) = make_ushort4(ls[0], ls[1], ls[2], ls[3]);
    } else {
        *(float4*)(dbc_bc + (size_t)row * 64 + dir * 32 + (c - DT_RANK)) =
            make_float4(vv[0], vv[1], vv[2], vv[3]);
    }
}

// ---------------- causal conv(4) + SiLU -> xsc16 (xs half only) ----------------
__global__ void conv_silu_kernel(
    const float* __restrict__ inp,
    const float* __restrict__ cw, const float* __restrict__ cb,
    __half* __restrict__ xsc16)
{
    const int idx = blockIdx.x * blockDim.x + threadIdx.x;
    if (idx >= BL * D_INNER) return;
    const int e = idx % D_INNER;
    const int row = idx / D_INNER;
    const int l = row & (SEQ - 1);
    const float w0 = cw[e * 4 + 0];
    const float w1 = cw[e * 4 + 1];
    const float w2 = cw[e * 4 + 2];
    const float w3 = cw[e * 4 + 3];
    const size_t base = (size_t)row * D_INNER + e;
    float acc = cb[e];
    acc = fmaf(w3, inp[base], acc);
    if (l >= 1) acc = fmaf(w2, inp[base - D_INNER], acc);
    if (l >= 2) acc = fmaf(w1, inp[base - 2 * D_INNER], acc);
    if (l >= 3) acc = fmaf(w0, inp[base - 3 * D_INNER], acc);
    const float xs = siluf(acc);
    unsigned short hi, lo;
    split_h(xs, hi, lo);
    unsigned short* o = (unsigned short*)xsc16 + (size_t)row * KOUT2 + e;
    o[0] = hi;
    o[D_INNER] = lo;
}

// ---------------- selective scan: 2 states/thread, 3-shfl reduction ----------------
__global__ void __launch_bounds__(256) scan_kernel(
    const __half* __restrict__ delta_f, const __half* __restrict__ delta_b,
    const float* __restrict__ dbc_bc,
    const float* __restrict__ A_log,  const float* __restrict__ A_b_log,
    const __half* __restrict__ xsc16,
    __half* __restrict__ y_f, __half* __restrict__ y_b)
{
    const int dir = blockIdx.z;
    const int b = blockIdx.y;
    const int e0 = blockIdx.x * 32;
    const int t = threadIdx.x;
    const int el = t >> 3;
    const int q = t & 7;
    const int e = e0 + el;
    const __half* delta = dir ? delta_b : delta_f;
    const float* Alog = dir ? A_b_log : A_log;
    __half* y = dir ? y_b : y_f;
    const float An0 = -__expf(Alog[e * D_STATE + q]);
    const float An1 = -__expf(Alog[e * D_STATE + q + 8]);

    __shared__ float s_d[16 * 32];
    __shared__ float s_x[16 * 32];
    __shared__ float s_bc[16 * 32];
    __shared__ float s_y[16 * 32];

    const int lj = t >> 5;
    const int lc = t & 31;
    float h0 = 0.f, h1 = 0.f;
    const size_t rowb = (size_t)b * SEQ;

    for (int c = 0; c < SEQ / 16; c++) {
#pragma unroll
        for (int rr = 0; rr < 2; rr++) {
            const int ljj = lj + rr * 8;
            const int i = c * 16 + ljj;
            const int l = dir ? (SEQ - 1 - i) : i;
            const size_t row = rowb + l;
            s_d[ljj * 32 + lc] = __half2float(delta[row * D_INNER + e0 + lc]);
            const __half xh = xsc16[row * KOUT2 + e0 + lc];
            const __half xl = xsc16[row * KOUT2 + D_INNER + e0 + lc];
            s_x[ljj * 32 + lc] = __half2float(xh) + __half2float(xl);
            s_bc[ljj * 32 + lc] = dbc_bc[row * 64 + dir * 32 + lc];
        }
        __syncthreads();

#pragma unroll
        for (int j = 0; j < 16; j++) {
            const float dlt = s_d[j * 32 + el];
            const float xv  = s_x[j * 32 + el];
            const float Bv0 = s_bc[j * 32 + q];
            const float Bv1 = s_bc[j * 32 + q + 8];
            const float Cv0 = s_bc[j * 32 + 16 + q];
            const float Cv1 = s_bc[j * 32 + 24 + q];
            const float dA0 = __expf(dlt * An0);
            const float dA1 = __expf(dlt * An1);
            const float dx = dlt * xv;
            h0 = fmaf(dA0, h0, dx * Bv0);
            h1 = fmaf(dA1, h1, dx * Bv1);
            float p = fmaf(h0, Cv0, h1 * Cv1);
            p += __shfl_xor_sync(0xffffffffu, p, 4);
            p += __shfl_xor_sync(0xffffffffu, p, 2);
            p += __shfl_xor_sync(0xffffffffu, p, 1);
            if (q == 0) s_y[j * 32 + el] = p;
        }
        __syncthreads();

#pragma unroll
        for (int rr = 0; rr < 2; rr++) {
            const int ljj = lj + rr * 8;
            const int i = c * 16 + ljj;
            const int l = dir ? (SEQ - 1 - i) : i;
            y[(rowb + l) * D_INNER + e0 + lc] = __float2half_rn(s_y[ljj * 32 + lc]);
        }
    }
}

// ---------------- fuse: u = (y_f + y_b + (D+D_b)*xs)*silu(z) -> fp16 pair ----------------
__global__ void fuse_kernel(
    const __half* __restrict__ yf, const __half* __restrict__ yb,
    const __half* __restrict__ xsc16, const __half* __restrict__ zs,
    const float* __restrict__ D1, const float* __restrict__ D2,
    __half* __restrict__ u2)
{
    const int idx4 = blockIdx.x * blockDim.x + threadIdx.x;
    if (idx4 >= (BL * D_INNER) / 4) return;
    const int e4 = (idx4 * 4) % D_INNER;
    const int r = (idx4 * 4) / D_INNER;
    const ushort4 av = *(const ushort4*)((const unsigned short*)yf + (size_t)idx4 * 4);
    const ushort4 bv = *(const ushort4*)((const unsigned short*)yb + (size_t)idx4 * 4);
    const ushort4 zv = *(const ushort4*)((const unsigned short*)zs + (size_t)idx4 * 4);
    const float4 d1 = *(const float4*)(D1 + e4);
    const float4 d2 = *(const float4*)(D2 + e4);
    const ushort4 xh = *(const ushort4*)((const unsigned short*)xsc16 + (size_t)r * KOUT2 + e4);
    const ushort4 xl = *(const ushort4*)((const unsigned short*)xsc16 + (size_t)r * KOUT2 + KOUT + e4);
    float xv[4];
    xv[0] = __half2float(__ushort_as_half(xh.x)) + __half2float(__ushort_as_half(xl.x));
    xv[1] = __half2float(__ushort_as_half(xh.y)) + __half2float(__ushort_as_half(xl.y));
    xv[2] = __half2float(__ushort_as_half(xh.z)) + __half2float(__ushort_as_half(xl.z));
    xv[3] = __half2float(__ushort_as_half(xh.w)) + __half2float(__ushort_as_half(xl.w));
    float ya[4], yb4[4], zf[4];
    ya[0] = __half2float(__ushort_as_half(av.x)); yb4[0] = __half2float(__ushort_as_half(bv.x));
    ya[1] = __half2float(__ushort_as_half(av.y)); yb4[1] = __half2float(__ushort_as_half(bv.y));
    ya[2] = __half2float(__ushort_as_half(av.z)); yb4[2] = __half2float(__ushort_as_half(bv.z));
    ya[3] = __half2float(__ushort_as_half(av.w)); yb4[3] = __half2float(__ushort_as_half(bv.w));
    zf[0] = __half2float(__ushort_as_half(zv.x));
    zf[1] = __half2float(__ushort_as_half(zv.y));
    zf[2] = __half2float(__ushort_as_half(zv.z));
    zf[3] = __half2float(__ushort_as_half(zv.w));
    float vv[4];
    vv[0] = (ya[0] + yb4[0] + (d1.x + d2.x) * xv[0]) * zf[0];
    vv[1] = (ya[1] + yb4[1] + (d1.y + d2.y) * xv[1]) * zf[1];
    vv[2] = (ya[2] + yb4[2] + (d1.z + d2.z) * xv[2]) * zf[2];
    vv[3] = (ya[3] + yb4[3] + (d1.w + d2.w) * xv[3]) * zf[3];
    unsigned short hs[4], ls[4];
#pragma unroll
    for (int j = 0; j < 4; j++) split_h(vv[j], hs[j], ls[j]);
    const size_t base = (size_t)r * KOUT2 + e4;
    *(ushort4*)((unsigned short*)u2 + base) = make_ushort4(hs[0], hs[1], hs[2], hs[3]);
    *(ushort4*)((unsigned short*)u2 + base + KOUT) = make_ushort4(ls[0], ls[1], ls[2], ls[3]);
}

// ---------------- out = sum of 3 out_proj slices ----------------
__global__ void addout3_kernel(float* __restrict__ out, const float* __restrict__ parts)
{
    const int i4 = blockIdx.x * blockDim.x + threadIdx.x;
    if (i4 * 4 >= BL * D_MODEL) return;
    const float4 a = *(const float4*)(parts + (size_t)i4 * 4);
    const float4 b = *(const float4*)(parts + (size_t)(BL * D_MODEL) + i4 * 4);
    const float4 c = *(const float4*)(parts + (size_t)(2 * BL * D_MODEL) + i4 * 4);
    *(float4*)(out + (size_t)i4 * 4) =
        make_float4(a.x + b.x + c.x, a.y + b.y + c.y, a.z + b.z + c.z, a.w + b.w + c.w);
}

// ---------------- launcher ----------------
extern "C" void kernel_launch(void* const* d_in, const int* in_sizes, int n_in,
                              void* d_out, int out_size)
{
    const float* x          = (const float*)d_in[0];
    const float* in_proj_w  = (const float*)d_in[1];
    const float* conv_w     = (const float*)d_in[2];
    const float* conv_bias  = (const float*)d_in[3];
    const float* x_proj_w   = (const float*)d_in[4];
    const float* dt_proj_w  = (const float*)d_in[5];
    const float* dt_proj_b  = (const float*)d_in[6];
    const float* A_log      = (const float*)d_in[7];
    const float* D_param    = (const float*)d_in[8];
    const float* out_proj_w = (const float*)d_in[9];
    const float* A_b_log    = (const float*)d_in[10];
    const float* x_proj_b_w = (const float*)d_in[11];
    const float* dt_proj_b_w= (const float*)d_in[12];
    const float* dt_proj_b_b= (const float*)d_in[13];
    const float* D_b        = (const float*)d_in[14];
    float* out = (float*)d_out;

    float *p_inp, *p_dbcp, *p_dbc_bc, *p_opart;
    __half *p_zs, *p_y_f, *p_y_b;
    __half *p_delta_f, *p_delta_b;
    __half *p_ax, *p_axh, *p_wi, *p_wiz, *p_xsc16, *p_w3, *p_wdtf, *p_wdtb;
    __half *p_d48f, *p_d48b, *p_u2, *p_wo;
    cudaGetSymbolAddress((void**)&p_inp, g_inp);
    cudaGetSymbolAddress((void**)&p_zs, g_zs);
    cudaGetSymbolAddress((void**)&p_dbcp, g_dbcp);
    cudaGetSymbolAddress((void**)&p_dbc_bc, g_dbc_bc);
    cudaGetSymbolAddress((void**)&p_delta_f, g_delta_f);
    cudaGetSymbolAddress((void**)&p_delta_b, g_delta_b);
    cudaGetSymbolAddress((void**)&p_y_f, g_y_f);
    cudaGetSymbolAddress((void**)&p_y_b, g_y_b);
    cudaGetSymbolAddress((void**)&p_opart, g_opart);
    cudaGetSymbolAddress((void**)&p_ax, g_ax);
    cudaGetSymbolAddress((void**)&p_axh, g_axh);
    cudaGetSymbolAddress((void**)&p_wi, g_wi);
    cudaGetSymbolAddress((void**)&p_wiz, g_wiz);
    cudaGetSymbolAddress((void**)&p_xsc16, g_xsc16);
    cudaGetSymbolAddress((void**)&p_w3, g_w3);
    cudaGetSymbolAddress((void**)&p_wdtf, g_wdt_f);
    cudaGetSymbolAddress((void**)&p_wdtb, g_wdt_b);
    cudaGetSymbolAddress((void**)&p_d48f, g_dbc48_f);
    cudaGetSymbolAddress((void**)&p_d48b, g_dbc48_b);
    cudaGetSymbolAddress((void**)&p_u2, g_u2);
    cudaGetSymbolAddress((void**)&p_wo, g_wo);

    const int SMEM_MMA = 4 * STAGE_BYTES; // 81920
    cudaFuncSetAttribute((const void*)hmma_f16_nt<0, 2, 0>,
                         cudaFuncAttributeMaxDynamicSharedMemorySize, SMEM_MMA);
    cudaFuncSetAttribute((const void*)hmma_f16_nt<0, 0, 1>,
                         cudaFuncAttributeMaxDynamicSharedMemorySize, SMEM_MMA);
    cudaFuncSetAttribute((const void*)hmma_f16_nt<0, 0, 0>,
                         cudaFuncAttributeMaxDynamicSharedMemorySize, SMEM_MMA);
    cudaFuncSetAttribute((const void*)hmma_f16_nt<2, 1, 0>,
                         cudaFuncAttributeMaxDynamicSharedMemorySize, SMEM_MMA);

    // 0) all operand splits in one launch
    prep_kernel<<<(PREP_TOTAL + 255) / 256, 256>>>(
        x, in_proj_w, out_proj_w, x_proj_w, x_proj_b_w, dt_proj_w, dt_proj_b_w,
        p_ax, p_axh, p_wi, p_wiz, p_wo, p_w3, p_wdtf, p_wdtb);

    // 1) in_proj mixed: z=0 xs-half fp16x2 -> fp32; z=1 z-half hi-only + silu -> zs fp16
    hmma_f16_nt<0, 2, 0><<<dim3(D_INNER / 128, BL / 128, 2), 256, SMEM_MMA>>>(
        p_ax, p_wi, p_inp, D_INNER, KIN2, KIN2 / 32, 0,
        nullptr, p_axh, p_wiz, (float*)p_zs, nullptr, KIN, KIN / 32);

    // 2) causal conv + silu -> xsc16 (xs half only)
    conv_silu_kernel<<<(BL * D_INNER + 255) / 256, 256>>>(
        p_inp, conv_w, conv_bias, p_xsc16);

    // 3) x_proj both dirs (padded N=256, split-K=8, padding stores skipped)
    hmma_f16_nt<0, 0, 1><<<dim3(DBC_PAD / 128, BL / 128, XPROJ_SPLITK), 256, SMEM_MMA>>>(
        p_xsc16, p_w3, p_dbcp, DBC_PAD, KOUT2, KOUT2 / 32 / XPROJ_SPLITK,
        (long long)BL * DBC_PAD, nullptr, nullptr, nullptr, nullptr, nullptr, 0, 0);

    // 4) combine partial strips -> d48 fp16 + compact B/C
    dbc48_combine_kernel<<<(BL * 160 / 4 + 255) / 256, 256>>>(
        p_dbcp, p_d48f, p_d48b, p_dbc_bc);

    // 5) delta_{f,b} = softplus(d48 @ wdt^T + bias) -> fp16
    hmma_f16_nt<2, 1, 0><<<dim3(D_INNER / 128, BL / 128, 2), 256, SMEM_MMA>>>(
        p_d48f, p_wdtf, (float*)p_delta_f, D_INNER, 2 * DT_RANK, (2 * DT_RANK) / 32, 0,
        dt_proj_b, p_d48b, p_wdtb, (float*)p_delta_b, dt_proj_b_b, 0, 0);

    // 6) selective scan -> y fp16
    scan_kernel<<<dim3(D_INNER / 32, NB, 2), 256>>>(
        p_delta_f, p_delta_b, p_dbc_bc, A_log, A_b_log, p_xsc16, p_y_f, p_y_b);

    // 7) fuse -> u fp16 pair
    fuse_kernel<<<(BL * D_INNER / 4 + 255) / 256, 256>>>(
        p_y_f, p_y_b, p_xsc16, p_zs, D_param, D_b, p_u2);

    // 8) out slices = u @ out_proj_w^T  (split-K=3)
    hmma_f16_nt<0, 0, 0><<<dim3(D_MODEL / 128, BL / 128, 3), 256, SMEM_MMA>>>(
        p_u2, p_wo, p_opart, D_MODEL, KOUT2, KOUT2 / 32 / 3, (long long)BL * D_MODEL,
        nullptr, nullptr, nullptr, nullptr, nullptr, 0, 0);
    addout3_kernel<<<(BL * D_MODEL / 4 + 255) / 256, 256>>>(out, p_opart);
}

// round 16
// speedup vs baseline: 1.0620x; 1.0140x over previous
#include <cuda_runtime.h>
#include <cuda_fp16.h>
#include <cstdint>
#include <cstddef>

// ---------------- problem constants ----------------
#define D_MODEL 768
#define D_INNER 1536
#define D_STATE 16
#define DT_RANK 48
#define NB 2
#define SEQ 1024
#define BL (NB * SEQ)                 // 2048
#define KIN  D_MODEL                  // 768
#define KIN2 (2 * KIN)                // 1536
#define KOUT D_INNER                  // 1536
#define KOUT2 (2 * KOUT)              // 3072
#define DBC_PAD 256
#define XPROJ_SPLITK 8

// ---------------- scratch (static __device__ arrays; zero-initialized) ----------------
__device__ float g_inp[BL * D_INNER];               // in_proj xs-half (fp32)
__device__ __half g_zs[BL * D_INNER];               // silu(z), from GEMM epilogue
__device__ float g_dbcp[XPROJ_SPLITK * BL * DBC_PAD];
__device__ float g_dbc_bc[BL * 64];
__device__ __half g_delta_f[BL * D_INNER];
__device__ __half g_delta_b[BL * D_INNER];
__device__ __half g_y_f[BL * D_INNER];
__device__ __half g_y_b[BL * D_INNER];
__device__ float g_opart[3 * BL * D_MODEL];
__device__ __half g_ax[BL * KIN2];                  // x split (hi|lo)
__device__ __half g_axh[BL * KIN];                  // x hi only
__device__ __half g_wi[D_INNER * KIN2];             // in_proj_w rows 0..1535 (hi|hi)
__device__ __half g_wiz[D_INNER * KIN];             // in_proj_w rows 1536..3071 (hi)
__device__ __half g_xsc16[BL * KOUT2];
__device__ __half g_w3[DBC_PAD * KOUT2];
__device__ __half g_wdt_f[D_INNER * 2 * DT_RANK];
__device__ __half g_wdt_b[D_INNER * 2 * DT_RANK];
__device__ __half g_dbc48_f[BL * 2 * DT_RANK];
__device__ __half g_dbc48_b[BL * 2 * DT_RANK];
__device__ __half g_u[BL * KOUT];                   // u hi-only fp16
__device__ __half g_wo[D_MODEL * KOUT];             // out_proj_w hi-only

// ---------------- math helpers ----------------
__device__ __forceinline__ float siluf(float x) { return x / (1.f + __expf(-x)); }
__device__ __forceinline__ float softplusf(float x) {
    return (x > 20.f) ? x : log1pf(__expf(x));
}
__device__ __forceinline__ uint32_t smem_u32(const void* p) {
    uint32_t a;
    asm("{ .reg .u64 t; cvta.to.shared.u64 t, %1; cvt.u32.u64 %0, t; }" : "=r"(a) : "l"(p));
    return a;
}
__device__ __forceinline__ void cp_async16(uint32_t saddr, const void* g) {
    asm volatile("cp.async.cg.shared.global [%0], [%1], 16;" :: "r"(saddr), "l"(g));
}
__device__ __forceinline__ void cp_commit() {
    asm volatile("cp.async.commit_group;" ::: "memory");
}
__device__ __forceinline__ void ldm_x4(uint32_t& r0, uint32_t& r1, uint32_t& r2,
                                       uint32_t& r3, uint32_t addr) {
    asm volatile("ldmatrix.sync.aligned.m8n8.x4.shared.b16 {%0,%1,%2,%3}, [%4];"
                 : "=r"(r0), "=r"(r1), "=r"(r2), "=r"(r3) : "r"(addr));
}
__device__ __forceinline__ void mma_f16(float* c, const uint32_t* a, const uint32_t* b) {
    asm volatile(
        "mma.sync.aligned.m16n8k16.row.col.f32.f16.f16.f32 "
        "{%0,%1,%2,%3}, {%4,%5,%6,%7}, {%8,%9}, {%0,%1,%2,%3};"
        : "+f"(c[0]), "+f"(c[1]), "+f"(c[2]), "+f"(c[3])
        : "r"(a[0]), "r"(a[1]), "r"(a[2]), "r"(a[3]), "r"(b[0]), "r"(b[1]));
}
__device__ __forceinline__ void split_h(float v, unsigned short& hi, unsigned short& lo) {
    __half h = __float2half_rn(v);
    __half l = __float2half_rn(v - __half2float(h));
    hi = __half_as_ushort(h); lo = __half_as_ushort(l);
}

// ---------------- HMMA fp16 GEMM ----------------
// EPI: 0 = fp32 store, 2 = softplus(v+bias)->half.
// ZMODE: 0 = split-K slices; 1 = two problems (shared Kp);
//        2 = mixed: z=0 -> fp32 C, z=1 -> (A2,B2,Kp2,nChunks2) silu->half into C2.
// SKIP80: skip stores where (gcol & 127) >= 80.
#define ROWB 80
#define STAGE_BYTES 20480
#define OFFB 10240
template <int EPI, int ZMODE, int SKIP80>
__global__ void __launch_bounds__(256) hmma_f16_nt(
    const __half* __restrict__ A,
    const __half* __restrict__ B,
    float* __restrict__ C, int ldc, int Kp, int nChunks, long long zstride,
    const float* __restrict__ bias,
    const __half* __restrict__ A2, const __half* __restrict__ B2,
    float* __restrict__ C2, const float* __restrict__ bias2,
    int Kp2, int nChunks2)
{
    extern __shared__ char smem[];
    const uint32_t sb = smem_u32(smem);
    const int tid = threadIdx.x;
    const int rowBase = blockIdx.y * 128;
    const int colBase = blockIdx.x * 128;
    float* Cw = nullptr;
    __half* CwH = nullptr;
    int chunkBase = 0;
    bool zsilu = false;
    if (ZMODE == 1) {
        if (blockIdx.z == 1) { A = A2; B = B2; C = C2; bias = bias2; }
        if (EPI == 2) CwH = (__half*)C; else Cw = C;
    } else if (ZMODE == 2) {
        if (blockIdx.z == 0) {
            Cw = C;
        } else {
            A = A2; B = B2; Kp = Kp2; nChunks = nChunks2;
            CwH = (__half*)C2; zsilu = true;
        }
    } else {
        Cw = C + (size_t)blockIdx.z * (size_t)zstride;
        chunkBase = blockIdx.z * nChunks;
    }

    const int r0 = tid >> 2, c0 = tid & 3;
    const int r1 = (tid + 256) >> 2, c1 = (tid + 256) & 3;
    const char* gA0 = (const char*)(A + (size_t)(rowBase + r0) * Kp + c0 * 8)
                      + (size_t)chunkBase * 64;
    const char* gA1 = (const char*)(A + (size_t)(rowBase + r1) * Kp + c1 * 8)
                      + (size_t)chunkBase * 64;
    const char* gB0 = (const char*)(B + (size_t)(colBase + r0) * Kp + c0 * 8)
                      + (size_t)chunkBase * 64;
    const char* gB1 = (const char*)(B + (size_t)(colBase + r1) * Kp + c1 * 8)
                      + (size_t)chunkBase * 64;
    const uint32_t sA0 = r0 * ROWB + c0 * 16, sA1 = r1 * ROWB + c1 * 16;
    const uint32_t sB0 = OFFB + sA0, sB1 = OFFB + sA1;

#define LOAD_STAGE(c) do {                                                  \
    const uint32_t _base = sb + ((c) & 3) * STAGE_BYTES;                    \
    const size_t _gk = (size_t)(c) * 64;                                    \
    cp_async16(_base + sA0, gA0 + _gk);                                     \
    cp_async16(_base + sA1, gA1 + _gk);                                     \
    cp_async16(_base + sB0, gB0 + _gk);                                     \
    cp_async16(_base + sB1, gB1 + _gk);                                     \
} while (0)

    const int wid = tid >> 5;
    const int l = tid & 31;
    const int wm = wid & 3;
    const int wn = wid >> 2;
    const int a_row = ((l >> 3) & 1) * 8 + (l & 7);
    const int a_k   = (l >> 4) * 8;
    const int b_n   = (l >> 4) * 8 + (l & 7);
    const int b_k   = ((l >> 3) & 1) * 8;

    float acc[2][8][4];
#pragma unroll
    for (int i = 0; i < 2; i++)
#pragma unroll
        for (int j = 0; j < 8; j++)
#pragma unroll
            for (int q = 0; q < 4; q++) acc[i][j][q] = 0.f;

    LOAD_STAGE(0); cp_commit();
    if (nChunks > 1) LOAD_STAGE(1);
    cp_commit();
    if (nChunks > 2) LOAD_STAGE(2);
    cp_commit();

    for (int c = 0; c < nChunks; c++) {
        asm volatile("cp.async.wait_group 2;" ::: "memory");
        __syncthreads();
        if (c + 3 < nChunks) LOAD_STAGE(c + 3);
        cp_commit();

        const uint32_t stb = sb + (c & 3) * STAGE_BYTES;
        const uint32_t aW = stb + (wm * 32) * ROWB;
        const uint32_t bW = stb + OFFB + (wn * 64) * ROWB;

        uint32_t a[2][2][4];
#pragma unroll
        for (int ks = 0; ks < 2; ks++)
#pragma unroll
            for (int mi = 0; mi < 2; mi++)
                ldm_x4(a[ks][mi][0], a[ks][mi][1], a[ks][mi][2], a[ks][mi][3],
                       aW + (mi * 16 + a_row) * ROWB + (ks * 16 + a_k) * 2);

        uint32_t b[3][4];
        ldm_x4(b[0][0], b[0][1], b[0][2], b[0][3], bW + b_n * ROWB + b_k * 2);
        ldm_x4(b[1][0], b[1][1], b[1][2], b[1][3], bW + (16 + b_n) * ROWB + b_k * 2);
#pragma unroll
        for (int i = 0; i < 8; i++) {
            if (i + 2 < 8) {
                const int ks2 = (i + 2) >> 2, nf2 = (i + 2) & 3;
                const int slot = (i + 2) % 3;
                ldm_x4(b[slot][0], b[slot][1], b[slot][2], b[slot][3],
                       bW + (nf2 * 16 + b_n) * ROWB + (ks2 * 16 + b_k) * 2);
            }
            const int ks = i >> 2, nf = i & 3;
            const uint32_t* bb = b[i % 3];
#pragma unroll
            for (int mi = 0; mi < 2; mi++) {
                mma_f16(acc[mi][nf * 2],     a[ks][mi], bb);
                mma_f16(acc[mi][nf * 2 + 1], a[ks][mi], bb + 2);
            }
        }
    }

    const int lrow = l >> 2;
    const int lcol = (l & 3) * 2;
#pragma unroll
    for (int mi = 0; mi < 2; mi++) {
        const int grow = rowBase + wm * 32 + mi * 16 + lrow;
#pragma unroll
        for (int nb = 0; nb < 8; nb++) {
            const int gcol = colBase + wn * 64 + nb * 8 + lcol;
            if (SKIP80 && (gcol & 127) >= 80) continue;
            float v0 = acc[mi][nb][0], v1 = acc[mi][nb][1];
            float v2 = acc[mi][nb][2], v3 = acc[mi][nb][3];
            if (ZMODE == 2 && zsilu) {
                *(__half2*)(CwH + (size_t)grow * ldc + gcol) =
                    __floats2half2_rn(siluf(v0), siluf(v1));
                *(__half2*)(CwH + (size_t)(grow + 8) * ldc + gcol) =
                    __floats2half2_rn(siluf(v2), siluf(v3));
            } else if (EPI == 2) {
                v0 = softplusf(v0 + bias[gcol]);
                v1 = softplusf(v1 + bias[gcol + 1]);
                v2 = softplusf(v2 + bias[gcol]);
                v3 = softplusf(v3 + bias[gcol + 1]);
                *(__half2*)(CwH + (size_t)grow * ldc + gcol) = __floats2half2_rn(v0, v1);
                *(__half2*)(CwH + (size_t)(grow + 8) * ldc + gcol) = __floats2half2_rn(v2, v3);
            } else {
                *(float2*)(Cw + (size_t)grow * ldc + gcol) = make_float2(v0, v1);
                *(float2*)(Cw + (size_t)(grow + 8) * ldc + gcol) = make_float2(v2, v3);
            }
        }
    }
#undef LOAD_STAGE
}

// ---------------- merged operand-prep kernel ----------------
#define SEG0 (BL * KIN / 4)                 // x -> ax (hi|lo) + axh (hi)
#define SEG1 (2 * D_INNER * KIN / 4)        // in_proj_w -> wi (hi|hi) / wiz (hi)
#define SEG2 (D_MODEL * KOUT / 4)           // out_proj_w -> wo (hi only)
#define SEG3 (2 * 80 * D_INNER / 4)         // x_proj -> w3 padded (hi|hi)
#define SEG4 (2 * D_INNER * DT_RANK / 4)    // dt_proj -> wdt (hi|hi)
#define PREP_TOTAL (SEG0 + SEG1 + SEG2 + SEG3 + SEG4)
__global__ void prep_kernel(
    const float* __restrict__ x, const float* __restrict__ in_w,
    const float* __restrict__ out_w,
    const float* __restrict__ xp_f, const float* __restrict__ xp_b,
    const float* __restrict__ dt_f, const float* __restrict__ dt_b,
    __half* __restrict__ ax, __half* __restrict__ axh,
    __half* __restrict__ wi, __half* __restrict__ wiz,
    __half* __restrict__ wo,
    __half* __restrict__ w3, __half* __restrict__ wdtf, __half* __restrict__ wdtb)
{
    int i4 = blockIdx.x * blockDim.x + threadIdx.x;
    if (i4 >= PREP_TOTAL) return;

    if (i4 < SEG0) {
        const int t = i4 * 4;
        const int r = t / KIN, k = t % KIN;
        const float4 v = *(const float4*)(x + t);
        float vv[4] = {v.x, v.y, v.z, v.w};
        unsigned short hs[4], ls[4];
#pragma unroll
        for (int j = 0; j < 4; j++) split_h(vv[j], hs[j], ls[j]);
        unsigned short* o = (unsigned short*)ax;
        const size_t base = (size_t)r * KIN2 + k;
        *(ushort4*)(o + base) = make_ushort4(hs[0], hs[1], hs[2], hs[3]);
        *(ushort4*)(o + base + KIN) = make_ushort4(ls[0], ls[1], ls[2], ls[3]);
        *(ushort4*)((unsigned short*)axh + t) = make_ushort4(hs[0], hs[1], hs[2], hs[3]);
        return;
    }
    i4 -= SEG0;
    if (i4 < SEG1) {
        const int t = i4 * 4;
        const int r = t / KIN, k = t % KIN;
        const float4 v = *(const float4*)(in_w + t);
        float vv[4] = {v.x, v.y, v.z, v.w};
        unsigned short hs[4], ls[4];
#pragma unroll
        for (int j = 0; j < 4; j++) split_h(vv[j], hs[j], ls[j]);
        const ushort4 H = make_ushort4(hs[0], hs[1], hs[2], hs[3]);
        if (r < D_INNER) {
            unsigned short* o = (unsigned short*)wi;
            const size_t base = (size_t)r * KIN2 + k;
            *(ushort4*)(o + base) = H;
            *(ushort4*)(o + base + KIN) = H;
        } else {
            unsigned short* o = (unsigned short*)wiz;
            *(ushort4*)(o + (size_t)(r - D_INNER) * KIN + k) = H;
        }
        return;
    }
    i4 -= SEG1;
    if (i4 < SEG2) {
        const int t = i4 * 4;
        const float4 v = *(const float4*)(out_w + t);
        float vv[4] = {v.x, v.y, v.z, v.w};
        unsigned short hs[4], ls[4];
#pragma unroll
        for (int j = 0; j < 4; j++) split_h(vv[j], hs[j], ls[j]);
        *(ushort4*)((unsigned short*)wo + t) = make_ushort4(hs[0], hs[1], hs[2], hs[3]);
        return;
    }
    i4 -= SEG2;
    if (i4 < SEG3) {
        const int t = i4 * 4;
        const int dir = t / (80 * D_INNER);
        const int rem = t % (80 * D_INNER);
        const int n = rem / D_INNER, k = rem % D_INNER;
        const float* w = dir ? xp_b : xp_f;
        const float4 v = *(const float4*)(w + (size_t)n * D_INNER + k);
        float vv[4] = {v.x, v.y, v.z, v.w};
        unsigned short hs[4], ls[4];
#pragma unroll
        for (int j = 0; j < 4; j++) split_h(vv[j], hs[j], ls[j]);
        unsigned short* o = (unsigned short*)w3;
        const size_t base = (size_t)(dir * 128 + n) * KOUT2 + k;
        *(ushort4*)(o + base) = make_ushort4(hs[0], hs[1], hs[2], hs[3]);
        *(ushort4*)(o + base + D_INNER) = make_ushort4(hs[0], hs[1], hs[2], hs[3]);
        return;
    }
    i4 -= SEG3;
    {
        const int t = i4 * 4;
        const int dir = t / (D_INNER * DT_RANK);
        const int rem = t % (D_INNER * DT_RANK);
        const int n = rem / DT_RANK, k = rem % DT_RANK;
        const float* w = dir ? dt_b : dt_f;
        unsigned short* o = (unsigned short*)(dir ? wdtb : wdtf);
        const float4 v = *(const float4*)(w + (size_t)n * DT_RANK + k);
        float vv[4] = {v.x, v.y, v.z, v.w};
        unsigned short hs[4], ls[4];
#pragma unroll
        for (int j = 0; j < 4; j++) split_h(vv[j], hs[j], ls[j]);
        const size_t base = (size_t)n * (2 * DT_RANK) + k;
        *(ushort4*)(o + base) = make_ushort4(hs[0], hs[1], hs[2], hs[3]);
        *(ushort4*)(o + base + DT_RANK) = make_ushort4(hs[0], hs[1], hs[2], hs[3]);
    }
}

// ---------------- combine x_proj split-K partials (80-col strips only) ----------------
__global__ void dbc48_combine_kernel(const float* __restrict__ parts,
                                     __half* __restrict__ d48f,
                                     __half* __restrict__ d48b,
                                     float* __restrict__ dbc_bc)
{
    const int i4 = blockIdx.x * blockDim.x + threadIdx.x;
    if (i4 * 4 >= BL * 160) return;
    const int t = i4 * 4;
    const int row = t / 160;
    const int rr = t % 160;
    const int dir = rr / 80;
    const int c = rr % 80;
    const size_t src = (size_t)row * DBC_PAD + dir * 128 + c;
    float vv[4] = {0.f, 0.f, 0.f, 0.f};
#pragma unroll
    for (int p = 0; p < XPROJ_SPLITK; p++) {
        const float4 v = *(const float4*)(parts + (size_t)p * (BL * DBC_PAD) + src);
        vv[0] += v.x; vv[1] += v.y; vv[2] += v.z; vv[3] += v.w;
    }
    if (c < DT_RANK) {
        unsigned short hs[4], ls[4];
#pragma unroll
        for (int j = 0; j < 4; j++) split_h(vv[j], hs[j], ls[j]);
        unsigned short* o = (unsigned short*)(dir ? d48b : d48f);
        const size_t base = (size_t)row * (2 * DT_RANK) + c;
        *(ushort4*)(o + base) = make_ushort4(hs[0], hs[1], hs[2], hs[3]);
        *(ushort4*)(o + base + DT_RANK) = make_ushort4(ls[0], ls[1], ls[2], ls[3]);
    } else {
        *(float4*)(dbc_bc + (size_t)row * 64 + dir * 32 + (c - DT_RANK)) =
            make_float4(vv[0], vv[1], vv[2], vv[3]);
    }
}

// ---------------- causal conv(4) + SiLU -> xsc16 (xs half only) ----------------
__global__ void conv_silu_kernel(
    const float* __restrict__ inp,
    const float* __restrict__ cw, const float* __restrict__ cb,
    __half* __restrict__ xsc16)
{
    const int idx = blockIdx.x * blockDim.x + threadIdx.x;
    if (idx >= BL * D_INNER) return;
    const int e = idx % D_INNER;
    const int row = idx / D_INNER;
    const int l = row & (SEQ - 1);
    const float w0 = cw[e * 4 + 0];
    const float w1 = cw[e * 4 + 1];
    const float w2 = cw[e * 4 + 2];
    const float w3 = cw[e * 4 + 3];
    const size_t base = (size_t)row * D_INNER + e;
    float acc = cb[e];
    acc = fmaf(w3, inp[base], acc);
    if (l >= 1) acc = fmaf(w2, inp[base - D_INNER], acc);
    if (l >= 2) acc = fmaf(w1, inp[base - 2 * D_INNER], acc);
    if (l >= 3) acc = fmaf(w0, inp[base - 3 * D_INNER], acc);
    const float xs = siluf(acc);
    unsigned short hi, lo;
    split_h(xs, hi, lo);
    unsigned short* o = (unsigned short*)xsc16 + (size_t)row * KOUT2 + e;
    o[0] = hi;
    o[D_INNER] = lo;
}

// ---------------- selective scan: 2 states/thread, 3-shfl reduction ----------------
__global__ void __launch_bounds__(256) scan_kernel(
    const __half* __restrict__ delta_f, const __half* __restrict__ delta_b,
    const float* __restrict__ dbc_bc,
    const float* __restrict__ A_log,  const float* __restrict__ A_b_log,
    const __half* __restrict__ xsc16,
    __half* __restrict__ y_f, __half* __restrict__ y_b)
{
    const int dir = blockIdx.z;
    const int b = blockIdx.y;
    const int e0 = blockIdx.x * 32;
    const int t = threadIdx.x;
    const int el = t >> 3;
    const int q = t & 7;
    const int e = e0 + el;
    const __half* delta = dir ? delta_b : delta_f;
    const float* Alog = dir ? A_b_log : A_log;
    __half* y = dir ? y_b : y_f;
    const float An0 = -__expf(Alog[e * D_STATE + q]);
    const float An1 = -__expf(Alog[e * D_STATE + q + 8]);

    __shared__ float s_d[16 * 32];
    __shared__ float s_x[16 * 32];
    __shared__ float s_bc[16 * 32];
    __shared__ float s_y[16 * 32];

    const int lj = t >> 5;
    const int lc = t & 31;
    float h0 = 0.f, h1 = 0.f;
    const size_t rowb = (size_t)b * SEQ;

    for (int c = 0; c < SEQ / 16; c++) {
#pragma unroll
        for (int rr = 0; rr < 2; rr++) {
            const int ljj = lj + rr * 8;
            const int i = c * 16 + ljj;
            const int l = dir ? (SEQ - 1 - i) : i;
            const size_t row = rowb + l;
            s_d[ljj * 32 + lc] = __half2float(delta[row * D_INNER + e0 + lc]);
            const __half xh = xsc16[row * KOUT2 + e0 + lc];
            const __half xl = xsc16[row * KOUT2 + D_INNER + e0 + lc];
            s_x[ljj * 32 + lc] = __half2float(xh) + __half2float(xl);
            s_bc[ljj * 32 + lc] = dbc_bc[row * 64 + dir * 32 + lc];
        }
        __syncthreads();

#pragma unroll
        for (int j = 0; j < 16; j++) {
            const float dlt = s_d[j * 32 + el];
            const float xv  = s_x[j * 32 + el];
            const float Bv0 = s_bc[j * 32 + q];
            const float Bv1 = s_bc[j * 32 + q + 8];
            const float Cv0 = s_bc[j * 32 + 16 + q];
            const float Cv1 = s_bc[j * 32 + 24 + q];
            const float dA0 = __expf(dlt * An0);
            const float dA1 = __expf(dlt * An1);
            const float dx = dlt * xv;
            h0 = fmaf(dA0, h0, dx * Bv0);
            h1 = fmaf(dA1, h1, dx * Bv1);
            float p = fmaf(h0, Cv0, h1 * Cv1);
            p += __shfl_xor_sync(0xffffffffu, p, 4);
            p += __shfl_xor_sync(0xffffffffu, p, 2);
            p += __shfl_xor_sync(0xffffffffu, p, 1);
            if (q == 0) s_y[j * 32 + el] = p;
        }
        __syncthreads();

#pragma unroll
        for (int rr = 0; rr < 2; rr++) {
            const int ljj = lj + rr * 8;
            const int i = c * 16 + ljj;
            const int l = dir ? (SEQ - 1 - i) : i;
            y[(rowb + l) * D_INNER + e0 + lc] = __float2half_rn(s_y[ljj * 32 + lc]);
        }
    }
}

// ---------------- fuse: u = (y_f + y_b + (D+D_b)*xs)*silu(z) -> fp16 hi-only ----------------
__global__ void fuse_kernel(
    const __half* __restrict__ yf, const __half* __restrict__ yb,
    const __half* __restrict__ xsc16, const __half* __restrict__ zs,
    const float* __restrict__ D1, const float* __restrict__ D2,
    __half* __restrict__ u)
{
    const int idx4 = blockIdx.x * blockDim.x + threadIdx.x;
    if (idx4 >= (BL * D_INNER) / 4) return;
    const int e4 = (idx4 * 4) % D_INNER;
    const int r = (idx4 * 4) / D_INNER;
    const ushort4 av = *(const ushort4*)((const unsigned short*)yf + (size_t)idx4 * 4);
    const ushort4 bv = *(const ushort4*)((const unsigned short*)yb + (size_t)idx4 * 4);
    const ushort4 zv = *(const ushort4*)((const unsigned short*)zs + (size_t)idx4 * 4);
    const float4 d1 = *(const float4*)(D1 + e4);
    const float4 d2 = *(const float4*)(D2 + e4);
    const ushort4 xh = *(const ushort4*)((const unsigned short*)xsc16 + (size_t)r * KOUT2 + e4);
    const ushort4 xl = *(const ushort4*)((const unsigned short*)xsc16 + (size_t)r * KOUT2 + KOUT + e4);
    float xv[4];
    xv[0] = __half2float(__ushort_as_half(xh.x)) + __half2float(__ushort_as_half(xl.x));
    xv[1] = __half2float(__ushort_as_half(xh.y)) + __half2float(__ushort_as_half(xl.y));
    xv[2] = __half2float(__ushort_as_half(xh.z)) + __half2float(__ushort_as_half(xl.z));
    xv[3] = __half2float(__ushort_as_half(xh.w)) + __half2float(__ushort_as_half(xl.w));
    float ya[4], yb4[4], zf[4];
    ya[0] = __half2float(__ushort_as_half(av.x)); yb4[0] = __half2float(__ushort_as_half(bv.x));
    ya[1] = __half2float(__ushort_as_half(av.y)); yb4[1] = __half2float(__ushort_as_half(bv.y));
    ya[2] = __half2float(__ushort_as_half(av.z)); yb4[2] = __half2float(__ushort_as_half(bv.z));
    ya[3] = __half2float(__ushort_as_half(av.w)); yb4[3] = __half2float(__ushort_as_half(bv.w));
    zf[0] = __half2float(__ushort_as_half(zv.x));
    zf[1] = __half2float(__ushort_as_half(zv.y));
    zf[2] = __half2float(__ushort_as_half(zv.z));
    zf[3] = __half2float(__ushort_as_half(zv.w));
    __half hu[4];
    hu[0] = __float2half_rn((ya[0] + yb4[0] + (d1.x + d2.x) * xv[0]) * zf[0]);
    hu[1] = __float2half_rn((ya[1] + yb4[1] + (d1.y + d2.y) * xv[1]) * zf[1]);
    hu[2] = __float2half_rn((ya[2] + yb4[2] + (d1.z + d2.z) * xv[2]) * zf[2]);
    hu[3] = __float2half_rn((ya[3] + yb4[3] + (d1.w + d2.w) * xv[3]) * zf[3]);
    *(ushort4*)((unsigned short*)u + (size_t)idx4 * 4) =
        make_ushort4(__half_as_ushort(hu[0]), __half_as_ushort(hu[1]),
                     __half_as_ushort(hu[2]), __half_as_ushort(hu[3]));
}

// ---------------- out = sum of 3 out_proj slices ----------------
__global__ void addout3_kernel(float* __restrict__ out, const float* __restrict__ parts)
{
    const int i4 = blockIdx.x * blockDim.x + threadIdx.x;
    if (i4 * 4 >= BL * D_MODEL) return;
    const float4 a = *(const float4*)(parts + (size_t)i4 * 4);
    const float4 b = *(const float4*)(parts + (size_t)(BL * D_MODEL) + i4 * 4);
    const float4 c = *(const float4*)(parts + (size_t)(2 * BL * D_MODEL) + i4 * 4);
    *(float4*)(out + (size_t)i4 * 4) =
        make_float4(a.x + b.x + c.x, a.y + b.y + c.y, a.z + b.z + c.z, a.w + b.w + c.w);
}

// ---------------- launcher ----------------
extern "C" void kernel_launch(void* const* d_in, const int* in_sizes, int n_in,
                              void* d_out, int out_size)
{
    const float* x          = (const float*)d_in[0];
    const float* in_proj_w  = (const float*)d_in[1];
    const float* conv_w     = (const float*)d_in[2];
    const float* conv_bias  = (const float*)d_in[3];
    const float* x_proj_w   = (const float*)d_in[4];
    const float* dt_proj_w  = (const float*)d_in[5];
    const float* dt_proj_b  = (const float*)d_in[6];
    const float* A_log      = (const float*)d_in[7];
    const float* D_param    = (const float*)d_in[8];
    const float* out_proj_w = (const float*)d_in[9];
    const float* A_b_log    = (const float*)d_in[10];
    const float* x_proj_b_w = (const float*)d_in[11];
    const float* dt_proj_b_w= (const float*)d_in[12];
    const float* dt_proj_b_b= (const float*)d_in[13];
    const float* D_b        = (const float*)d_in[14];
    float* out = (float*)d_out;

    float *p_inp, *p_dbcp, *p_dbc_bc, *p_opart;
    __half *p_zs, *p_y_f, *p_y_b;
    __half *p_delta_f, *p_delta_b;
    __half *p_ax, *p_axh, *p_wi, *p_wiz, *p_xsc16, *p_w3, *p_wdtf, *p_wdtb;
    __half *p_d48f, *p_d48b, *p_u, *p_wo;
    cudaGetSymbolAddress((void**)&p_inp, g_inp);
    cudaGetSymbolAddress((void**)&p_zs, g_zs);
    cudaGetSymbolAddress((void**)&p_dbcp, g_dbcp);
    cudaGetSymbolAddress((void**)&p_dbc_bc, g_dbc_bc);
    cudaGetSymbolAddress((void**)&p_delta_f, g_delta_f);
    cudaGetSymbolAddress((void**)&p_delta_b, g_delta_b);
    cudaGetSymbolAddress((void**)&p_y_f, g_y_f);
    cudaGetSymbolAddress((void**)&p_y_b, g_y_b);
    cudaGetSymbolAddress((void**)&p_opart, g_opart);
    cudaGetSymbolAddress((void**)&p_ax, g_ax);
    cudaGetSymbolAddress((void**)&p_axh, g_axh);
    cudaGetSymbolAddress((void**)&p_wi, g_wi);
    cudaGetSymbolAddress((void**)&p_wiz, g_wiz);
    cudaGetSymbolAddress((void**)&p_xsc16, g_xsc16);
    cudaGetSymbolAddress((void**)&p_w3, g_w3);
    cudaGetSymbolAddress((void**)&p_wdtf, g_wdt_f);
    cudaGetSymbolAddress((void**)&p_wdtb, g_wdt_b);
    cudaGetSymbolAddress((void**)&p_d48f, g_dbc48_f);
    cudaGetSymbolAddress((void**)&p_d48b, g_dbc48_b);
    cudaGetSymbolAddress((void**)&p_u, g_u);
    cudaGetSymbolAddress((void**)&p_wo, g_wo);

    const int SMEM_MMA = 4 * STAGE_BYTES; // 81920
    cudaFuncSetAttribute((const void*)hmma_f16_nt<0, 2, 0>,
                         cudaFuncAttributeMaxDynamicSharedMemorySize, SMEM_MMA);
    cudaFuncSetAttribute((const void*)hmma_f16_nt<0, 0, 1>,
                         cudaFuncAttributeMaxDynamicSharedMemorySize, SMEM_MMA);
    cudaFuncSetAttribute((const void*)hmma_f16_nt<0, 0, 0>,
                         cudaFuncAttributeMaxDynamicSharedMemorySize, SMEM_MMA);
    cudaFuncSetAttribute((const void*)hmma_f16_nt<2, 1, 0>,
                         cudaFuncAttributeMaxDynamicSharedMemorySize, SMEM_MMA);

    // 0) all operand splits in one launch
    prep_kernel<<<(PREP_TOTAL + 255) / 256, 256>>>(
        x, in_proj_w, out_proj_w, x_proj_w, x_proj_b_w, dt_proj_w, dt_proj_b_w,
        p_ax, p_axh, p_wi, p_wiz, p_wo, p_w3, p_wdtf, p_wdtb);

    // 1) in_proj mixed: z=0 xs-half fp16x2 -> fp32; z=1 z-half hi-only + silu -> zs fp16
    hmma_f16_nt<0, 2, 0><<<dim3(D_INNER / 128, BL / 128, 2), 256, SMEM_MMA>>>(
        p_ax, p_wi, p_inp, D_INNER, KIN2, KIN2 / 32, 0,
        nullptr, p_axh, p_wiz, (float*)p_zs, nullptr, KIN, KIN / 32);

    // 2) causal conv + silu -> xsc16 (xs half only)
    conv_silu_kernel<<<(BL * D_INNER + 255) / 256, 256>>>(
        p_inp, conv_w, conv_bias, p_xsc16);

    // 3) x_proj both dirs (padded N=256, split-K=8, padding stores skipped)
    hmma_f16_nt<0, 0, 1><<<dim3(DBC_PAD / 128, BL / 128, XPROJ_SPLITK), 256, SMEM_MMA>>>(
        p_xsc16, p_w3, p_dbcp, DBC_PAD, KOUT2, KOUT2 / 32 / XPROJ_SPLITK,
        (long long)BL * DBC_PAD, nullptr, nullptr, nullptr, nullptr, nullptr, 0, 0);

    // 4) combine partial strips -> d48 fp16 + compact B/C
    dbc48_combine_kernel<<<(BL * 160 / 4 + 255) / 256, 256>>>(
        p_dbcp, p_d48f, p_d48b, p_dbc_bc);

    // 5) delta_{f,b} = softplus(d48 @ wdt^T + bias) -> fp16
    hmma_f16_nt<2, 1, 0><<<dim3(D_INNER / 128, BL / 128, 2), 256, SMEM_MMA>>>(
        p_d48f, p_wdtf, (float*)p_delta_f, D_INNER, 2 * DT_RANK, (2 * DT_RANK) / 32, 0,
        dt_proj_b, p_d48b, p_wdtb, (float*)p_delta_b, dt_proj_b_b, 0, 0);

    // 6) selective scan -> y fp16
    scan_kernel<<<dim3(D_INNER / 32, NB, 2), 256>>>(
        p_delta_f, p_delta_b, p_dbc_bc, A_log, A_b_log, p_xsc16, p_y_f, p_y_b);

    // 7) fuse -> u fp16 hi-only
    fuse_kernel<<<(BL * D_INNER / 4 + 255) / 256, 256>>>(
        p_y_f, p_y_b, p_xsc16, p_zs, D_param, D_b, p_u);

    // 8) out slices = u @ wo^T  (hi-only K=1536, split-K=3 -> 16 chunks each)
    hmma_f16_nt<0, 0, 0><<<dim3(D_MODEL / 128, BL / 128, 3), 256, SMEM_MMA>>>(
        p_u, p_wo, p_opart, D_MODEL, KOUT, KOUT / 32 / 3, (long long)BL * D_MODEL,
        nullptr, nullptr, nullptr, nullptr, nullptr, 0, 0);
    addout3_kernel<<<(BL * D_MODEL / 4 + 255) / 256, 256>>>(out, p_opart);
}

// round 17
// speedup vs baseline: 1.1581x; 1.0905x over previous
#include <cuda_runtime.h>
#include <cuda_fp16.h>
#include <cstdint>
#include <cstddef>

// ---------------- problem constants ----------------
#define D_MODEL 768
#define D_INNER 1536
#define D_STATE 16
#define DT_RANK 48
#define NB 2
#define SEQ 1024
#define BL (NB * SEQ)                 // 2048
#define KIN  D_MODEL                  // 768
#define KOUT D_INNER                  // 1536
#define KOUT2 (2 * KOUT)              // 3072
#define DBC_PAD 256
#define XPROJ_SPLITK 8

// ---------------- scratch (static __device__ arrays; zero-initialized) ----------------
__device__ float g_inp[BL * D_INNER];               // in_proj xs-half (fp32)
__device__ __half g_zs[BL * D_INNER];               // silu(z), from GEMM epilogue
__device__ float g_dbcp[XPROJ_SPLITK * BL * DBC_PAD];
__device__ float g_dbc_bc[BL * 64];
__device__ __half g_delta_f[BL * D_INNER];
__device__ __half g_delta_b[BL * D_INNER];
__device__ __half g_y_f[BL * D_INNER];
__device__ __half g_y_b[BL * D_INNER];
__device__ float g_opart[3 * BL * D_MODEL];
__device__ __half g_axh[BL * KIN];                  // x hi only
__device__ __half g_wih[D_INNER * KIN];             // in_proj_w rows 0..1535 (hi)
__device__ __half g_wiz[D_INNER * KIN];             // in_proj_w rows 1536..3071 (hi)
__device__ __half g_xsc16[BL * KOUT2];              // xsc split (hi|lo)
__device__ __half g_w3[DBC_PAD * KOUT2];
__device__ __half g_wdt_f[D_INNER * 2 * DT_RANK];
__device__ __half g_wdt_b[D_INNER * 2 * DT_RANK];
__device__ __half g_dbc48_f[BL * 2 * DT_RANK];
__device__ __half g_dbc48_b[BL * 2 * DT_RANK];
__device__ __half g_u[BL * KOUT];                   // u hi-only fp16
__device__ __half g_wo[D_MODEL * KOUT];             // out_proj_w hi-only

// ---------------- math helpers ----------------
__device__ __forceinline__ float siluf(float x) { return x / (1.f + __expf(-x)); }
__device__ __forceinline__ float softplusf(float x) {
    return (x > 20.f) ? x : log1pf(__expf(x));
}
__device__ __forceinline__ uint32_t smem_u32(const void* p) {
    uint32_t a;
    asm("{ .reg .u64 t; cvta.to.shared.u64 t, %1; cvt.u32.u64 %0, t; }" : "=r"(a) : "l"(p));
    return a;
}
__device__ __forceinline__ void cp_async16(uint32_t saddr, const void* g) {
    asm volatile("cp.async.cg.shared.global [%0], [%1], 16;" :: "r"(saddr), "l"(g));
}
__device__ __forceinline__ void cp_commit() {
    asm volatile("cp.async.commit_group;" ::: "memory");
}
__device__ __forceinline__ void ldm_x4(uint32_t& r0, uint32_t& r1, uint32_t& r2,
                                       uint32_t& r3, uint32_t addr) {
    asm volatile("ldmatrix.sync.aligned.m8n8.x4.shared.b16 {%0,%1,%2,%3}, [%4];"
                 : "=r"(r0), "=r"(r1), "=r"(r2), "=r"(r3) : "r"(addr));
}
__device__ __forceinline__ void mma_f16(float* c, const uint32_t* a, const uint32_t* b) {
    asm volatile(
        "mma.sync.aligned.m16n8k16.row.col.f32.f16.f16.f32 "
        "{%0,%1,%2,%3}, {%4,%5,%6,%7}, {%8,%9}, {%0,%1,%2,%3};"
        : "+f"(c[0]), "+f"(c[1]), "+f"(c[2]), "+f"(c[3])
        : "r"(a[0]), "r"(a[1]), "r"(a[2]), "r"(a[3]), "r"(b[0]), "r"(b[1]));
}
__device__ __forceinline__ void split_h(float v, unsigned short& hi, unsigned short& lo) {
    __half h = __float2half_rn(v);
    __half l = __float2half_rn(v - __half2float(h));
    hi = __half_as_ushort(h); lo = __half_as_ushort(l);
}

// ---------------- HMMA fp16 GEMM ----------------
// EPI: 0 = fp32 store, 2 = softplus(v+bias)->half.
// ZMODE: 0 = split-K slices; 1 = two problems (shared Kp);
//        2 = mixed: z=0 -> fp32 C, z=1 -> (A2,B2,Kp2,nChunks2) silu->half into C2.
// SKIP80: skip stores where (gcol & 127) >= 80.
#define ROWB 80
#define STAGE_BYTES 20480
#define OFFB 10240
template <int EPI, int ZMODE, int SKIP80>
__global__ void __launch_bounds__(256) hmma_f16_nt(
    const __half* __restrict__ A,
    const __half* __restrict__ B,
    float* __restrict__ C, int ldc, int Kp, int nChunks, long long zstride,
    const float* __restrict__ bias,
    const __half* __restrict__ A2, const __half* __restrict__ B2,
    float* __restrict__ C2, const float* __restrict__ bias2,
    int Kp2, int nChunks2)
{
    extern __shared__ char smem[];
    const uint32_t sb = smem_u32(smem);
    const int tid = threadIdx.x;
    const int rowBase = blockIdx.y * 128;
    const int colBase = blockIdx.x * 128;
    float* Cw = nullptr;
    __half* CwH = nullptr;
    int chunkBase = 0;
    bool zsilu = false;
    if (ZMODE == 1) {
        if (blockIdx.z == 1) { A = A2; B = B2; C = C2; bias = bias2; }
        if (EPI == 2) CwH = (__half*)C; else Cw = C;
    } else if (ZMODE == 2) {
        if (blockIdx.z == 0) {
            Cw = C;
        } else {
            A = A2; B = B2; Kp = Kp2; nChunks = nChunks2;
            CwH = (__half*)C2; zsilu = true;
        }
    } else {
        Cw = C + (size_t)blockIdx.z * (size_t)zstride;
        chunkBase = blockIdx.z * nChunks;
    }

    const int r0 = tid >> 2, c0 = tid & 3;
    const int r1 = (tid + 256) >> 2, c1 = (tid + 256) & 3;
    const char* gA0 = (const char*)(A + (size_t)(rowBase + r0) * Kp + c0 * 8)
                      + (size_t)chunkBase * 64;
    const char* gA1 = (const char*)(A + (size_t)(rowBase + r1) * Kp + c1 * 8)
                      + (size_t)chunkBase * 64;
    const char* gB0 = (const char*)(B + (size_t)(colBase + r0) * Kp + c0 * 8)
                      + (size_t)chunkBase * 64;
    const char* gB1 = (const char*)(B + (size_t)(colBase + r1) * Kp + c1 * 8)
                      + (size_t)chunkBase * 64;
    const uint32_t sA0 = r0 * ROWB + c0 * 16, sA1 = r1 * ROWB + c1 * 16;
    const uint32_t sB0 = OFFB + sA0, sB1 = OFFB + sA1;

#define LOAD_STAGE(c) do {                                                  \
    const uint32_t _base = sb + ((c) & 3) * STAGE_BYTES;                    \
    const size_t _gk = (size_t)(c) * 64;                                    \
    cp_async16(_base + sA0, gA0 + _gk);                                     \
    cp_async16(_base + sA1, gA1 + _gk);                                     \
    cp_async16(_base + sB0, gB0 + _gk);                                     \
    cp_async16(_base + sB1, gB1 + _gk);                                     \
} while (0)

    const int wid = tid >> 5;
    const int l = tid & 31;
    const int wm = wid & 3;
    const int wn = wid >> 2;
    const int a_row = ((l >> 3) & 1) * 8 + (l & 7);
    const int a_k   = (l >> 4) * 8;
    const int b_n   = (l >> 4) * 8 + (l & 7);
    const int b_k   = ((l >> 3) & 1) * 8;

    float acc[2][8][4];
#pragma unroll
    for (int i = 0; i < 2; i++)
#pragma unroll
        for (int j = 0; j < 8; j++)
#pragma unroll
            for (int q = 0; q < 4; q++) acc[i][j][q] = 0.f;

    LOAD_STAGE(0); cp_commit();
    if (nChunks > 1) LOAD_STAGE(1);
    cp_commit();
    if (nChunks > 2) LOAD_STAGE(2);
    cp_commit();

    for (int c = 0; c < nChunks; c++) {
        asm volatile("cp.async.wait_group 2;" ::: "memory");
        __syncthreads();
        if (c + 3 < nChunks) LOAD_STAGE(c + 3);
        cp_commit();

        const uint32_t stb = sb + (c & 3) * STAGE_BYTES;
        const uint32_t aW = stb + (wm * 32) * ROWB;
        const uint32_t bW = stb + OFFB + (wn * 64) * ROWB;

        uint32_t a[2][2][4];
#pragma unroll
        for (int ks = 0; ks < 2; ks++)
#pragma unroll
            for (int mi = 0; mi < 2; mi++)
                ldm_x4(a[ks][mi][0], a[ks][mi][1], a[ks][mi][2], a[ks][mi][3],
                       aW + (mi * 16 + a_row) * ROWB + (ks * 16 + a_k) * 2);

        uint32_t b[3][4];
        ldm_x4(b[0][0], b[0][1], b[0][2], b[0][3], bW + b_n * ROWB + b_k * 2);
        ldm_x4(b[1][0], b[1][1], b[1][2], b[1][3], bW + (16 + b_n) * ROWB + b_k * 2);
#pragma unroll
        for (int i = 0; i < 8; i++) {
            if (i + 2 < 8) {
                const int ks2 = (i + 2) >> 2, nf2 = (i + 2) & 3;
                const int slot = (i + 2) % 3;
                ldm_x4(b[slot][0], b[slot][1], b[slot][2], b[slot][3],
                       bW + (nf2 * 16 + b_n) * ROWB + (ks2 * 16 + b_k) * 2);
            }
            const int ks = i >> 2, nf = i & 3;
            const uint32_t* bb = b[i % 3];
#pragma unroll
            for (int mi = 0; mi < 2; mi++) {
                mma_f16(acc[mi][nf * 2],     a[ks][mi], bb);
                mma_f16(acc[mi][nf * 2 + 1], a[ks][mi], bb + 2);
            }
        }
    }

    const int lrow = l >> 2;
    const int lcol = (l & 3) * 2;
#pragma unroll
    for (int mi = 0; mi < 2; mi++) {
        const int grow = rowBase + wm * 32 + mi * 16 + lrow;
#pragma unroll
        for (int nb = 0; nb < 8; nb++) {
            const int gcol = colBase + wn * 64 + nb * 8 + lcol;
            if (SKIP80 && (gcol & 127) >= 80) continue;
            float v0 = acc[mi][nb][0], v1 = acc[mi][nb][1];
            float v2 = acc[mi][nb][2], v3 = acc[mi][nb][3];
            if (ZMODE == 2 && zsilu) {
                *(__half2*)(CwH + (size_t)grow * ldc + gcol) =
                    __floats2half2_rn(siluf(v0), siluf(v1));
                *(__half2*)(CwH + (size_t)(grow + 8) * ldc + gcol) =
                    __floats2half2_rn(siluf(v2), siluf(v3));
            } else if (EPI == 2) {
                v0 = softplusf(v0 + bias[gcol]);
                v1 = softplusf(v1 + bias[gcol + 1]);
                v2 = softplusf(v2 + bias[gcol]);
                v3 = softplusf(v3 + bias[gcol + 1]);
                *(__half2*)(CwH + (size_t)grow * ldc + gcol) = __floats2half2_rn(v0, v1);
                *(__half2*)(CwH + (size_t)(grow + 8) * ldc + gcol) = __floats2half2_rn(v2, v3);
            } else {
                *(float2*)(Cw + (size_t)grow * ldc + gcol) = make_float2(v0, v1);
                *(float2*)(Cw + (size_t)(grow + 8) * ldc + gcol) = make_float2(v2, v3);
            }
        }
    }
#undef LOAD_STAGE
}

// ---------------- merged operand-prep kernel ----------------
#define SEG0 (BL * KIN / 4)                 // x -> axh (hi)
#define SEG1 (2 * D_INNER * KIN / 4)        // in_proj_w -> wih / wiz (hi)
#define SEG2 (D_MODEL * KOUT / 4)           // out_proj_w -> wo (hi)
#define SEG3 (2 * 80 * D_INNER / 4)         // x_proj -> w3 padded (hi|hi)
#define SEG4 (2 * D_INNER * DT_RANK / 4)    // dt_proj -> wdt (hi|hi)
#define PREP_TOTAL (SEG0 + SEG1 + SEG2 + SEG3 + SEG4)
__global__ void prep_kernel(
    const float* __restrict__ x, const float* __restrict__ in_w,
    const float* __restrict__ out_w,
    const float* __restrict__ xp_f, const float* __restrict__ xp_b,
    const float* __restrict__ dt_f, const float* __restrict__ dt_b,
    __half* __restrict__ axh,
    __half* __restrict__ wih, __half* __restrict__ wiz,
    __half* __restrict__ wo,
    __half* __restrict__ w3, __half* __restrict__ wdtf, __half* __restrict__ wdtb)
{
    int i4 = blockIdx.x * blockDim.x + threadIdx.x;
    if (i4 >= PREP_TOTAL) return;

    if (i4 < SEG0) {
        const int t = i4 * 4;
        const float4 v = *(const float4*)(x + t);
        float vv[4] = {v.x, v.y, v.z, v.w};
        unsigned short hs[4], ls[4];
#pragma unroll
        for (int j = 0; j < 4; j++) split_h(vv[j], hs[j], ls[j]);
        *(ushort4*)((unsigned short*)axh + t) = make_ushort4(hs[0], hs[1], hs[2], hs[3]);
        return;
    }
    i4 -= SEG0;
    if (i4 < SEG1) {
        const int t = i4 * 4;
        const int r = t / KIN, k = t % KIN;
        const float4 v = *(const float4*)(in_w + t);
        float vv[4] = {v.x, v.y, v.z, v.w};
        unsigned short hs[4], ls[4];
#pragma unroll
        for (int j = 0; j < 4; j++) split_h(vv[j], hs[j], ls[j]);
        const ushort4 H = make_ushort4(hs[0], hs[1], hs[2], hs[3]);
        if (r < D_INNER) {
            *(ushort4*)((unsigned short*)wih + (size_t)r * KIN + k) = H;
        } else {
            *(ushort4*)((unsigned short*)wiz + (size_t)(r - D_INNER) * KIN + k) = H;
        }
        return;
    }
    i4 -= SEG1;
    if (i4 < SEG2) {
        const int t = i4 * 4;
        const float4 v = *(const float4*)(out_w + t);
        float vv[4] = {v.x, v.y, v.z, v.w};
        unsigned short hs[4], ls[4];
#pragma unroll
        for (int j = 0; j < 4; j++) split_h(vv[j], hs[j], ls[j]);
        *(ushort4*)((unsigned short*)wo + t) = make_ushort4(hs[0], hs[1], hs[2], hs[3]);
        return;
    }
    i4 -= SEG2;
    if (i4 < SEG3) {
        const int t = i4 * 4;
        const int dir = t / (80 * D_INNER);
        const int rem = t % (80 * D_INNER);
        const int n = rem / D_INNER, k = rem % D_INNER;
        const float* w = dir ? xp_b : xp_f;
        const float4 v = *(const float4*)(w + (size_t)n * D_INNER + k);
        float vv[4] = {v.x, v.y, v.z, v.w};
        unsigned short hs[4], ls[4];
#pragma unroll
        for (int j = 0; j < 4; j++) split_h(vv[j], hs[j], ls[j]);
        unsigned short* o = (unsigned short*)w3;
        const size_t base = (size_t)(dir * 128 + n) * KOUT2 + k;
        *(ushort4*)(o + base) = make_ushort4(hs[0], hs[1], hs[2], hs[3]);
        *(ushort4*)(o + base + D_INNER) = make_ushort4(hs[0], hs[1], hs[2], hs[3]);
        return;
    }
    i4 -= SEG3;
    {
        const int t = i4 * 4;
        const int dir = t / (D_INNER * DT_RANK);
        const int rem = t % (D_INNER * DT_RANK);
        const int n = rem / DT_RANK, k = rem % DT_RANK;
        const float* w = dir ? dt_b : dt_f;
        unsigned short* o = (unsigned short*)(dir ? wdtb : wdtf);
        const float4 v = *(const float4*)(w + (size_t)n * DT_RANK + k);
        float vv[4] = {v.x, v.y, v.z, v.w};
        unsigned short hs[4], ls[4];
#pragma unroll
        for (int j = 0; j < 4; j++) split_h(vv[j], hs[j], ls[j]);
        const size_t base = (size_t)n * (2 * DT_RANK) + k;
        *(ushort4*)(o + base) = make_ushort4(hs[0], hs[1], hs[2], hs[3]);
        *(ushort4*)(o + base + DT_RANK) = make_ushort4(hs[0], hs[1], hs[2], hs[3]);
    }
}

// ---------------- combine x_proj split-K partials (80-col strips only) ----------------
__global__ void dbc48_combine_kernel(const float* __restrict__ parts,
                                     __half* __restrict__ d48f,
                                     __half* __restrict__ d48b,
                                     float* __restrict__ dbc_bc)
{
    const int i4 = blockIdx.x * blockDim.x + threadIdx.x;
    if (i4 * 4 >= BL * 160) return;
    const int t = i4 * 4;
    const int row = t / 160;
    const int rr = t % 160;
    const int dir = rr / 80;
    const int c = rr % 80;
    const size_t src = (size_t)row * DBC_PAD + dir * 128 + c;
    float vv[4] = {0.f, 0.f, 0.f, 0.f};
#pragma unroll
    for (int p = 0; p < XPROJ_SPLITK; p++) {
        const float4 v = *(const float4*)(parts + (size_t)p * (BL * DBC_PAD) + src);
        vv[0] += v.x; vv[1] += v.y; vv[2] += v.z; vv[3] += v.w;
    }
    if (c < DT_RANK) {
        unsigned short hs[4], ls[4];
#pragma unroll
        for (int j = 0; j < 4; j++) split_h(vv[j], hs[j], ls[j]);
        unsigned short* o = (unsigned short*)(dir ? d48b : d48f);
        const size_t base = (size_t)row * (2 * DT_RANK) + c;
        *(ushort4*)(o + base) = make_ushort4(hs[0], hs[1], hs[2], hs[3]);
        *(ushort4*)(o + base + DT_RANK) = make_ushort4(ls[0], ls[1], ls[2], ls[3]);
    } else {
        *(float4*)(dbc_bc + (size_t)row * 64 + dir * 32 + (c - DT_RANK)) =
            make_float4(vv[0], vv[1], vv[2], vv[3]);
    }
}

// ---------------- causal conv(4) + SiLU -> xsc16 (xs half only) ----------------
__global__ void conv_silu_kernel(
    const float* __restrict__ inp,
    const float* __restrict__ cw, const float* __restrict__ cb,
    __half* __restrict__ xsc16)
{
    const int idx = blockIdx.x * blockDim.x + threadIdx.x;
    if (idx >= BL * D_INNER) return;
    const int e = idx % D_INNER;
    const int row = idx / D_INNER;
    const int l = row & (SEQ - 1);
    const float w0 = cw[e * 4 + 0];
    const float w1 = cw[e * 4 + 1];
    const float w2 = cw[e * 4 + 2];
    const float w3 = cw[e * 4 + 3];
    const size_t base = (size_t)row * D_INNER + e;
    float acc = cb[e];
    acc = fmaf(w3, inp[base], acc);
    if (l >= 1) acc = fmaf(w2, inp[base - D_INNER], acc);
    if (l >= 2) acc = fmaf(w1, inp[base - 2 * D_INNER], acc);
    if (l >= 3) acc = fmaf(w0, inp[base - 3 * D_INNER], acc);
    const float xs = siluf(acc);
    unsigned short hi, lo;
    split_h(xs, hi, lo);
    unsigned short* o = (unsigned short*)xsc16 + (size_t)row * KOUT2 + e;
    o[0] = hi;
    o[D_INNER] = lo;
}

// ---------------- selective scan: 2 states/thread, 3-shfl reduction ----------------
__global__ void __launch_bounds__(256) scan_kernel(
    const __half* __restrict__ delta_f, const __half* __restrict__ delta_b,
    const float* __restrict__ dbc_bc,
    const float* __restrict__ A_log,  const float* __restrict__ A_b_log,
    const __half* __restrict__ xsc16,
    __half* __restrict__ y_f, __half* __restrict__ y_b)
{
    const int dir = blockIdx.z;
    const int b = blockIdx.y;
    const int e0 = blockIdx.x * 32;
    const int t = threadIdx.x;
    const int el = t >> 3;
    const int q = t & 7;
    const int e = e0 + el;
    const __half* delta = dir ? delta_b : delta_f;
    const float* Alog = dir ? A_b_log : A_log;
    __half* y = dir ? y_b : y_f;
    const float An0 = -__expf(Alog[e * D_STATE + q]);
    const float An1 = -__expf(Alog[e * D_STATE + q + 8]);

    __shared__ float s_d[16 * 32];
    __shared__ float s_x[16 * 32];
    __shared__ float s_bc[16 * 32];
    __shared__ float s_y[16 * 32];

    const int lj = t >> 5;
    const int lc = t & 31;
    float h0 = 0.f, h1 = 0.f;
    const size_t rowb = (size_t)b * SEQ;

    for (int c = 0; c < SEQ / 16; c++) {
#pragma unroll
        for (int rr = 0; rr < 2; rr++) {
            const int ljj = lj + rr * 8;
            const int i = c * 16 + ljj;
            const int l = dir ? (SEQ - 1 - i) : i;
            const size_t row = rowb + l;
            s_d[ljj * 32 + lc] = __half2float(delta[row * D_INNER + e0 + lc]);
            const __half xh = xsc16[row * KOUT2 + e0 + lc];
            const __half xl = xsc16[row * KOUT2 + D_INNER + e0 + lc];
            s_x[ljj * 32 + lc] = __half2float(xh) + __half2float(xl);
            s_bc[ljj * 32 + lc] = dbc_bc[row * 64 + dir * 32 + lc];
        }
        __syncthreads();

#pragma unroll
        for (int j = 0; j < 16; j++) {
            const float dlt = s_d[j * 32 + el];
            const float xv  = s_x[j * 32 + el];
            const float Bv0 = s_bc[j * 32 + q];
            const float Bv1 = s_bc[j * 32 + q + 8];
            const float Cv0 = s_bc[j * 32 + 16 + q];
            const float Cv1 = s_bc[j * 32 + 24 + q];
            const float dA0 = __expf(dlt * An0);
            const float dA1 = __expf(dlt * An1);
            const float dx = dlt * xv;
            h0 = fmaf(dA0, h0, dx * Bv0);
            h1 = fmaf(dA1, h1, dx * Bv1);
            float p = fmaf(h0, Cv0, h1 * Cv1);
            p += __shfl_xor_sync(0xffffffffu, p, 4);
            p += __shfl_xor_sync(0xffffffffu, p, 2);
            p += __shfl_xor_sync(0xffffffffu, p, 1);
            if (q == 0) s_y[j * 32 + el] = p;
        }
        __syncthreads();

#pragma unroll
        for (int rr = 0; rr < 2; rr++) {
            const int ljj = lj + rr * 8;
            const int i = c * 16 + ljj;
            const int l = dir ? (SEQ - 1 - i) : i;
            y[(rowb + l) * D_INNER + e0 + lc] = __float2half_rn(s_y[ljj * 32 + lc]);
        }
    }
}

// ---------------- fuse: u = (y_f + y_b + (D+D_b)*xs)*silu(z) -> fp16 hi-only ----------------
__global__ void fuse_kernel(
    const __half* __restrict__ yf, const __half* __restrict__ yb,
    const __half* __restrict__ xsc16, const __half* __restrict__ zs,
    const float* __restrict__ D1, const float* __restrict__ D2,
    __half* __restrict__ u)
{
    const int idx4 = blockIdx.x * blockDim.x + threadIdx.x;
    if (idx4 >= (BL * D_INNER) / 4) return;
    const int e4 = (idx4 * 4) % D_INNER;
    const int r = (idx4 * 4) / D_INNER;
    const ushort4 av = *(const ushort4*)((const unsigned short*)yf + (size_t)idx4 * 4);
    const ushort4 bv = *(const ushort4*)((const unsigned short*)yb + (size_t)idx4 * 4);
    const ushort4 zv = *(const ushort4*)((const unsigned short*)zs + (size_t)idx4 * 4);
    const float4 d1 = *(const float4*)(D1 + e4);
    const float4 d2 = *(const float4*)(D2 + e4);
    const ushort4 xh = *(const ushort4*)((const unsigned short*)xsc16 + (size_t)r * KOUT2 + e4);
    const ushort4 xl = *(const ushort4*)((const unsigned short*)xsc16 + (size_t)r * KOUT2 + KOUT + e4);
    float xv[4];
    xv[0] = __half2float(__ushort_as_half(xh.x)) + __half2float(__ushort_as_half(xl.x));
    xv[1] = __half2float(__ushort_as_half(xh.y)) + __half2float(__ushort_as_half(xl.y));
    xv[2] = __half2float(__ushort_as_half(xh.z)) + __half2float(__ushort_as_half(xl.z));
    xv[3] = __half2float(__ushort_as_half(xh.w)) + __half2float(__ushort_as_half(xl.w));
    float ya[4], yb4[4], zf[4];
    ya[0] = __half2float(__ushort_as_half(av.x)); yb4[0] = __half2float(__ushort_as_half(bv.x));
    ya[1] = __half2float(__ushort_as_half(av.y)); yb4[1] = __half2float(__ushort_as_half(bv.y));
    ya[2] = __half2float(__ushort_as_half(av.z)); yb4[2] = __half2float(__ushort_as_half(bv.z));
    ya[3] = __half2float(__ushort_as_half(av.w)); yb4[3] = __half2float(__ushort_as_half(bv.w));
    zf[0] = __half2float(__ushort_as_half(zv.x));
    zf[1] = __half2float(__ushort_as_half(zv.y));
    zf[2] = __half2float(__ushort_as_half(zv.z));
    zf[3] = __half2float(__ushort_as_half(zv.w));
    __half hu[4];
    hu[0] = __float2half_rn((ya[0] + yb4[0] + (d1.x + d2.x) * xv[0]) * zf[0]);
    hu[1] = __float2half_rn((ya[1] + yb4[1] + (d1.y + d2.y) * xv[1]) * zf[1]);
    hu[2] = __float2half_rn((ya[2] + yb4[2] + (d1.z + d2.z) * xv[2]) * zf[2]);
    hu[3] = __float2half_rn((ya[3] + yb4[3] + (d1.w + d2.w) * xv[3]) * zf[3]);
    *(ushort4*)((unsigned short*)u + (size_t)idx4 * 4) =
        make_ushort4(__half_as_ushort(hu[0]), __half_as_ushort(hu[1]),
                     __half_as_ushort(hu[2]), __half_as_ushort(hu[3]));
}

// ---------------- out = sum of 3 out_proj slices ----------------
__global__ void addout3_kernel(float* __restrict__ out, const float* __restrict__ parts)
{
    const int i4 = blockIdx.x * blockDim.x + threadIdx.x;
    if (i4 * 4 >= BL * D_MODEL) return;
    const float4 a = *(const float4*)(parts + (size_t)i4 * 4);
    const float4 b = *(const float4*)(parts + (size_t)(BL * D_MODEL) + i4 * 4);
    const float4 c = *(const float4*)(parts + (size_t)(2 * BL * D_MODEL) + i4 * 4);
    *(float4*)(out + (size_t)i4 * 4) =
        make_float4(a.x + b.x + c.x, a.y + b.y + c.y, a.z + b.z + c.z, a.w + b.w + c.w);
}

// ---------------- launcher ----------------
extern "C" void kernel_launch(void* const* d_in, const int* in_sizes, int n_in,
                              void* d_out, int out_size)
{
    const float* x          = (const float*)d_in[0];
    const float* in_proj_w  = (const float*)d_in[1];
    const float* conv_w     = (const float*)d_in[2];
    const float* conv_bias  = (const float*)d_in[3];
    const float* x_proj_w   = (const float*)d_in[4];
    const float* dt_proj_w  = (const float*)d_in[5];
    const float* dt_proj_b  = (const float*)d_in[6];
    const float* A_log      = (const float*)d_in[7];
    const float* D_param    = (const float*)d_in[8];
    const float* out_proj_w = (const float*)d_in[9];
    const float* A_b_log    = (const float*)d_in[10];
    const float* x_proj_b_w = (const float*)d_in[11];
    const float* dt_proj_b_w= (const float*)d_in[12];
    const float* dt_proj_b_b= (const float*)d_in[13];
    const float* D_b        = (const float*)d_in[14];
    float* out = (float*)d_out;

    float *p_inp, *p_dbcp, *p_dbc_bc, *p_opart;
    __half *p_zs, *p_y_f, *p_y_b;
    __half *p_delta_f, *p_delta_b;
    __half *p_axh, *p_wih, *p_wiz, *p_xsc16, *p_w3, *p_wdtf, *p_wdtb;
    __half *p_d48f, *p_d48b, *p_u, *p_wo;
    cudaGetSymbolAddress((void**)&p_inp, g_inp);
    cudaGetSymbolAddress((void**)&p_zs, g_zs);
    cudaGetSymbolAddress((void**)&p_dbcp, g_dbcp);
    cudaGetSymbolAddress((void**)&p_dbc_bc, g_dbc_bc);
    cudaGetSymbolAddress((void**)&p_delta_f, g_delta_f);
    cudaGetSymbolAddress((void**)&p_delta_b, g_delta_b);
    cudaGetSymbolAddress((void**)&p_y_f, g_y_f);
    cudaGetSymbolAddress((void**)&p_y_b, g_y_b);
    cudaGetSymbolAddress((void**)&p_opart, g_opart);
    cudaGetSymbolAddress((void**)&p_axh, g_axh);
    cudaGetSymbolAddress((void**)&p_wih, g_wih);
    cudaGetSymbolAddress((void**)&p_wiz, g_wiz);
    cudaGetSymbolAddress((void**)&p_xsc16, g_xsc16);
    cudaGetSymbolAddress((void**)&p_w3, g_w3);
    cudaGetSymbolAddress((void**)&p_wdtf, g_wdt_f);
    cudaGetSymbolAddress((void**)&p_wdtb, g_wdt_b);
    cudaGetSymbolAddress((void**)&p_d48f, g_dbc48_f);
    cudaGetSymbolAddress((void**)&p_d48b, g_dbc48_b);
    cudaGetSymbolAddress((void**)&p_u, g_u);
    cudaGetSymbolAddress((void**)&p_wo, g_wo);

    const int SMEM_MMA = 4 * STAGE_BYTES; // 81920
    cudaFuncSetAttribute((const void*)hmma_f16_nt<0, 2, 0>,
                         cudaFuncAttributeMaxDynamicSharedMemorySize, SMEM_MMA);
    cudaFuncSetAttribute((const void*)hmma_f16_nt<0, 0, 1>,
                         cudaFuncAttributeMaxDynamicSharedMemorySize, SMEM_MMA);
    cudaFuncSetAttribute((const void*)hmma_f16_nt<0, 0, 0>,
                         cudaFuncAttributeMaxDynamicSharedMemorySize, SMEM_MMA);
    cudaFuncSetAttribute((const void*)hmma_f16_nt<2, 1, 0>,
                         cudaFuncAttributeMaxDynamicSharedMemorySize, SMEM_MMA);

    // 0) all operand splits in one launch
    prep_kernel<<<(PREP_TOTAL + 255) / 256, 256>>>(
        x, in_proj_w, out_proj_w, x_proj_w, x_proj_b_w, dt_proj_w, dt_proj_b_w,
        p_axh, p_wih, p_wiz, p_wo, p_w3, p_wdtf, p_wdtb);

    // 1) in_proj mixed (both hi-only, K=768, 24 chunks each):
    //    z=0 xs-half -> fp32 g_inp; z=1 z-half + silu -> zs fp16
    hmma_f16_nt<0, 2, 0><<<dim3(D_INNER / 128, BL / 128, 2), 256, SMEM_MMA>>>(
        p_axh, p_wih, p_inp, D_INNER, KIN, KIN / 32, 0,
        nullptr, p_axh, p_wiz, (float*)p_zs, nullptr, KIN, KIN / 32);

    // 2) causal conv + silu -> xsc16 (xs half only)
    conv_silu_kernel<<<(BL * D_INNER + 255) / 256, 256>>>(
        p_inp, conv_w, conv_bias, p_xsc16);

    // 3) x_proj both dirs (padded N=256, split-K=8, padding stores skipped)
    hmma_f16_nt<0, 0, 1><<<dim3(DBC_PAD / 128, BL / 128, XPROJ_SPLITK), 256, SMEM_MMA>>>(
        p_xsc16, p_w3, p_dbcp, DBC_PAD, KOUT2, KOUT2 / 32 / XPROJ_SPLITK,
        (long long)BL * DBC_PAD, nullptr, nullptr, nullptr, nullptr, nullptr, 0, 0);

    // 4) combine partial strips -> d48 fp16 + compact B/C
    dbc48_combine_kernel<<<(BL * 160 / 4 + 255) / 256, 256>>>(
        p_dbcp, p_d48f, p_d48b, p_dbc_bc);

    // 5) delta_{f,b} = softplus(d48 @ wdt^T + bias) -> fp16
    hmma_f16_nt<2, 1, 0><<<dim3(D_INNER / 128, BL / 128, 2), 256, SMEM_MMA>>>(
        p_d48f, p_wdtf, (float*)p_delta_f, D_INNER, 2 * DT_RANK, (2 * DT_RANK) / 32, 0,
        dt_proj_b, p_d48b, p_wdtb, (float*)p_delta_b, dt_proj_b_b, 0, 0);

    // 6) selective scan -> y fp16
    scan_kernel<<<dim3(D_INNER / 32, NB, 2), 256>>>(
        p_delta_f, p_delta_b, p_dbc_bc, A_log, A_b_log, p_xsc16, p_y_f, p_y_b);

    // 7) fuse -> u fp16 hi-only
    fuse_kernel<<<(BL * D_INNER / 4 + 255) / 256, 256>>>(
        p_y_f, p_y_b, p_xsc16, p_zs, D_param, D_b, p_u);

    // 8) out slices = u @ wo^T  (hi-only K=1536, split-K=3 -> 16 chunks each)
    hmma_f16_nt<0, 0, 0><<<dim3(D_MODEL / 128, BL / 128, 3), 256, SMEM_MMA>>>(
        p_u, p_wo, p_opart, D_MODEL, KOUT, KOUT / 32 / 3, (long long)BL * D_MODEL,
        nullptr, nullptr, nullptr, nullptr, nullptr, 0, 0);
    addout3_kernel<<<(BL * D_MODEL / 4 + 255) / 256, 256>>>(out, p_opart);
}